// round 12
// baseline (speedup 1.0000x reference)
#include <cuda_runtime.h>
#include <cuda_fp16.h>
#include <cstdint>

#define B_  16
#define L_  96
#define D_  512
#define M_  (B_ * L_)
#define PSTRIDE (B_ * L_ * L_)
#define NSLICE 8                        // pairwise h-slices (64 each)
#define NTILE 32                        // 16 b x 2 i-tiles

// ---------------- device scratch ------------------------------------------
__device__ float g_AB2[M_ * D_];       // [b][hp][i]: (a+b1)*|w2|, permuted h
__device__ float g_C2[M_ * D_];        // [b][hp][j]: c*|w2|, permuted h
__device__ float g_P[NSLICE * PSTRIDE];
__device__ float g_v4[4 * M_];         // v partials per GEMM n-block
__device__ float g_partial[NTILE];
__device__ float g_b1s[D_];            // b1[h]*|w2[h]| at permuted index
__device__ int   g_Hpos;
__device__ int   g_ctrT[NTILE];        // per-(b,it) arrival counters
__device__ int   g_ctr;                // global arrival counter
__device__ __half g_Xf[M_ * D_];
__device__ __half g_Wt[1024 * D_];     // [n][k], |w2|-scaled, perm rows

// ---------------- helpers ---------------------------------------------------
__device__ __forceinline__ uint32_t smem_u32(const void* p) {
    uint32_t a;
    asm("{ .reg .u64 t; cvta.to.shared.u64 t, %1; cvt.u32.u64 %0, t; }"
        : "=r"(a) : "l"(p));
    return a;
}
__device__ __forceinline__ void ldsm_x4(uint32_t* r, uint32_t addr) {
    asm volatile("ldmatrix.sync.aligned.m8n8.x4.shared.b16 {%0,%1,%2,%3}, [%4];"
                 : "=r"(r[0]), "=r"(r[1]), "=r"(r[2]), "=r"(r[3]) : "r"(addr));
}
__device__ __forceinline__ void mma_f16(float* c, const uint32_t* a,
                                        uint32_t b0, uint32_t b1) {
    asm volatile(
        "mma.sync.aligned.m16n8k16.row.col.f32.f16.f16.f32 "
        "{%0,%1,%2,%3}, {%4,%5,%6,%7}, {%8,%9}, {%0,%1,%2,%3};"
        : "+f"(c[0]), "+f"(c[1]), "+f"(c[2]), "+f"(c[3])
        : "r"(a[0]), "r"(a[1]), "r"(a[2]), "r"(a[3]), "r"(b0), "r"(b1));
}
__device__ __forceinline__ void cp_async16(uint32_t saddr, const void* gaddr) {
    asm volatile("cp.async.cg.shared.global [%0], [%1], 16;"
                 :: "r"(saddr), "l"(gaddr));
}

// ---------------- kernel A: convert (X -> fp16) + (W1 -> scaled/perm T) ----
__global__ void __launch_bounds__(512)
convert_kernel(const float* __restrict__ X, const float* __restrict__ W1,
               const float* __restrict__ W2, const float* __restrict__ b1) {
    const int tid = threadIdx.x;
    const int bx = blockIdx.x;
    if (bx < 384) {
        int idx = bx * 512 + tid;                 // over 196608 float4
        float4 v = ((const float4*)X)[idx];
        ((__half2*)g_Xf)[idx * 2 + 0] = __floats2half2_rn(v.x, v.y);
        ((__half2*)g_Xf)[idx * 2 + 1] = __floats2half2_rn(v.z, v.w);
    } else {
        __shared__ float t[32][33];
        __shared__ int   sperm[512];
        __shared__ float sw2a[512];
        __shared__ int   wcnt[16], wpre[17];

        // inlined deterministic sign-partition of h by sign(w2)
        const int lane = tid & 31, w = tid >> 5;
        float v2 = W2[tid];
        bool pos = (v2 >= 0.f);
        unsigned mset = __ballot_sync(0xffffffffu, pos);
        int lpre = __popc(mset & ((1u << lane) - 1u));
        if (lane == 0) wcnt[w] = __popc(mset);
        __syncthreads();
        if (tid == 0) {
            int s = 0;
#pragma unroll
            for (int k = 0; k < 16; k++) { wpre[k] = s; s += wcnt[k]; }
            wpre[16] = s;
        }
        __syncthreads();
        const int Hp = wpre[16];
        int posrank = wpre[w] + lpre;
        sperm[tid] = pos ? posrank : (Hp + tid - posrank);
        sw2a[tid] = fabsf(v2);
        __syncthreads();

        const int wb = bx - 384;                  // 0..511
        const int p  = wb >> 8;
        const int k0 = ((wb >> 4) & 15) * 32;
        const int n0 = (wb & 15) * 32;
        const int tx = tid & 31, ty = tid >> 5;   // (32,16)

        if (wb == 0 && tid == 0) g_Hpos = Hp;
        if (p == 0 && k0 == 0 && tid < 32) {
            int h = n0 + tid;
            g_b1s[sperm[h]] = b1[h] * sw2a[h];
        }
#pragma unroll
        for (int r = 0; r < 32; r += 16)
            t[ty + r][tx] = W1[(size_t)(p * 512 + k0 + ty + r) * 512 + n0 + tx];
        __syncthreads();
#pragma unroll
        for (int r = 0; r < 32; r += 16) {
            const int h = n0 + ty + r;
            float v = t[tx][ty + r] * sw2a[h];
            size_t o = (size_t)(p * 512 + sperm[h]) * 512 + k0 + tx;
            g_Wt[o] = __float2half_rn(v);
        }
    }
}

// ---------------- kernel B: single-pass fp16 GEMM via mma.sync --------------
#define GASTRIDE 80
#define G_ATILE (128 * GASTRIDE)        // 10240
#define G_STAGE (2 * G_ATILE)           // 20480
#define GEMM_SMEM (3 * G_STAGE)         // 61440

__global__ void __launch_bounds__(256, 1)
gemm_mma_kernel() {
    extern __shared__ char smem[];
    const uint32_t smem_base = smem_u32(smem);
    const int tid = threadIdx.x, wid = tid >> 5, lane = tid & 31;
    const int n0 = blockIdx.x * 128;
    const int m0 = blockIdx.y * 128;
    const int m_off = (wid & 3) * 32;
    const int n_off = (wid >> 2) * 64;

    const __half* srcA = g_Xf + (size_t)m0 * 512;
    const __half* srcB = g_Wt + (size_t)n0 * 512;

    const bool isArow = (tid < 128);
    const __half* prow = isArow ? (srcA + (size_t)tid * 512)
                                : (srcB + (size_t)(tid - 128) * 512);
    const uint32_t pdst = (isArow ? tid * GASTRIDE
                                  : G_ATILE + (tid - 128) * GASTRIDE);

    auto prefetch = [&](int c, int buf) {
        const uint32_t d = smem_base + buf * G_STAGE + pdst;
        const __half* s = prow + c * 32;
#pragma unroll
        for (int q = 0; q < 4; q++)
            cp_async16(d + q * 16, s + q * 8);
    };

    float acc[2][8][4];
#pragma unroll
    for (int i = 0; i < 2; i++)
#pragma unroll
        for (int j = 0; j < 8; j++)
#pragma unroll
            for (int k = 0; k < 4; k++) acc[i][j][k] = 0.f;

    const int grp = lane >> 3, ln8 = lane & 7;
    const int a_row = (grp & 1) * 8 + ln8;
    const int a_kB  = (grp >> 1) * 16;
    const int b_row = ((grp >> 1) & 1) * 8 + ln8;
    const int b_kB  = (grp & 1) * 16;

    prefetch(0, 0);
    asm volatile("cp.async.commit_group;" ::: "memory");
    prefetch(1, 1);
    asm volatile("cp.async.commit_group;" ::: "memory");

    for (int c = 0; c < 16; c++) {
        if (c + 2 < 16) {
            asm volatile("cp.async.wait_group 1;" ::: "memory");
        } else {
            asm volatile("cp.async.wait_group 0;" ::: "memory");
        }
        __syncthreads();
        if (c + 2 < 16) {
            prefetch(c + 2, (c + 2) % 3);
            asm volatile("cp.async.commit_group;" ::: "memory");
        }

        const uint32_t base = smem_base + (c % 3) * G_STAGE;
        const uint32_t Bb = base + G_ATILE;
#pragma unroll
        for (int ks = 0; ks < 2; ks++) {
            const int kB = ks * 32;
            uint32_t a[2][4], b[4][4];
#pragma unroll
            for (int fm = 0; fm < 2; fm++)
                ldsm_x4(a[fm], base + (m_off + fm * 16 + a_row) * GASTRIDE
                                    + kB + a_kB);
#pragma unroll
            for (int fp = 0; fp < 4; fp++)
                ldsm_x4(b[fp], Bb + (n_off + fp * 16 + b_row) * GASTRIDE
                                  + kB + b_kB);
#pragma unroll
            for (int fm = 0; fm < 2; fm++)
#pragma unroll
                for (int fp = 0; fp < 4; fp++) {
                    mma_f16(acc[fm][2 * fp + 0], a[fm], b[fp][0], b[fp][1]);
                    mma_f16(acc[fm][2 * fp + 1], a[fm], b[fp][2], b[fp][3]);
                }
        }
        __syncthreads();
    }

    const bool isA = (n0 < 512);
    const int nbase = isA ? n0 : (n0 - 512);
    const int r0 = lane >> 2, cc = (lane & 3) * 2;

    // ---- C-half blocks: signed column sums -> g_v4 (deterministic) ----
    if (!isA) {
        const int Hpos = g_Hpos;
        float s[4] = {0.f, 0.f, 0.f, 0.f};
#pragma unroll
        for (int fm = 0; fm < 2; fm++)
#pragma unroll
            for (int fn = 0; fn < 8; fn++)
#pragma unroll
                for (int e = 0; e < 2; e++) {
                    const int l = n_off + fn * 8 + cc + e;
                    const float sg = (nbase + l < Hpos) ? 1.f : -1.f;
                    s[fm * 2 + 0] += sg * acc[fm][fn][e];
                    s[fm * 2 + 1] += sg * acc[fm][fn][2 + e];
                }
#pragma unroll
        for (int q = 0; q < 4; q++) {
            s[q] += __shfl_xor_sync(0xffffffffu, s[q], 1);
            s[q] += __shfl_xor_sync(0xffffffffu, s[q], 2);
        }
        float* svv = (float*)smem;
        if (wid < 4 && (lane & 3) == 0) {
            svv[m_off +  0 + r0] = s[0];
            svv[m_off +  8 + r0] = s[1];
            svv[m_off + 16 + r0] = s[2];
            svv[m_off + 24 + r0] = s[3];
        }
        __syncthreads();
        if (wid >= 4 && (lane & 3) == 0) {
            svv[m_off +  0 + r0] += s[0];
            svv[m_off +  8 + r0] += s[1];
            svv[m_off + 16 + r0] += s[2];
            svv[m_off + 24 + r0] += s[3];
        }
        __syncthreads();
        if (tid < 128)
            g_v4[(blockIdx.x - 4) * M_ + m0 + tid] = svv[tid];
    }

    // b1s table for A-half blocks
    float* sb1 = (float*)smem;
    if (isA) {
        if (tid < 128) sb1[tid] = g_b1s[n0 + tid];
        __syncthreads();
    }

    // epilogue: straight write, rows already permuted/scaled via Wt
    float* dstBase = isA ? g_AB2 : g_C2;
#pragma unroll
    for (int fm = 0; fm < 2; fm++) {
        const int mr0 = m0 + m_off + fm * 16 + r0;
        const int mr1 = mr0 + 8;
        const int b0r = mr0 / 96, i0r = mr0 - b0r * 96;
        const int b1r = mr1 / 96, i1r = mr1 - b1r * 96;
#pragma unroll
        for (int fn = 0; fn < 8; fn++) {
            const int lc = n_off + fn * 8 + cc;
            const float* a4 = acc[fm][fn];
#pragma unroll
            for (int e = 0; e < 2; e++) {
                const int l = lc + e;
                const float add = isA ? sb1[l] : 0.f;
                dstBase[((size_t)(b0r * 512 + nbase + l)) * 96 + i0r] = a4[e] + add;
                dstBase[((size_t)(b1r * 512 + nbase + l)) * 96 + i1r] = a4[2 + e] + add;
            }
        }
    }
}

// ---------------- kernel D: pairwise abs-sum + fused CE tail ---------------
// grid (8 h-slices, 2 i-tiles, 16 b); 256 thr; 3x6 per thread.
// Last-arriving slice block per (b,it) reduces 8 P slices -> logits -> CE.
__global__ void __launch_bounds__(256)
pairwise_kernel(const int* __restrict__ order, float* __restrict__ out) {
    __shared__ __align__(16) float buf[64 * 48 + 64 * 96];  // 36 KB, reused
    float* As = buf;                 // [64][48]
    float* Cs = buf + 64 * 48;       // [64][96]

    const int hs = blockIdx.x;
    const int it = blockIdx.y;
    const int b  = blockIdx.z;
    const int tid = threadIdx.x;
    const int warp = tid >> 5, lane = tid & 31;
    const int ty = tid >> 4, tx = tid & 15;
    const int il = 3 * ty, jl = 6 * tx;

    const float4* srcA = (const float4*)(g_AB2 +
        ((size_t)(b * 512 + hs * 64)) * 96 + it * 48);
    const float4* srcC = (const float4*)(g_C2 +
        ((size_t)(b * 512 + hs * 64)) * 96);
    float4* dA = (float4*)As;
    float4* dC = (float4*)Cs;
#pragma unroll
    for (int t = tid; t < 768; t += 256) {
        int r = t / 12, q = t - r * 12;
        dA[t] = srcA[r * 24 + q];
    }
#pragma unroll
    for (int t = tid; t < 1536; t += 256)
        dC[t] = srcC[t];
    __syncthreads();

    const int bnd = min(max(g_Hpos - hs * 64, 0), 64);
    float acc[3][6] = {{0.f}};

    int h = 0;
#pragma unroll 4
    for (; h < bnd; h++) {
        const float* Ar = &As[h * 48 + il];
        const float* Cr = &Cs[h * 96 + jl];
        float a0 = Ar[0], a1 = Ar[1], a2 = Ar[2];
        float2 c01 = *(const float2*)&Cr[0];
        float2 c23 = *(const float2*)&Cr[2];
        float2 c45 = *(const float2*)&Cr[4];
        float cv[6] = {c01.x, c01.y, c23.x, c23.y, c45.x, c45.y};
#pragma unroll
        for (int c = 0; c < 6; c++) {
            acc[0][c] += fabsf(a0 + cv[c]);
            acc[1][c] += fabsf(a1 + cv[c]);
            acc[2][c] += fabsf(a2 + cv[c]);
        }
    }
#pragma unroll 4
    for (; h < 64; h++) {
        const float* Ar = &As[h * 48 + il];
        const float* Cr = &Cs[h * 96 + jl];
        float a0 = Ar[0], a1 = Ar[1], a2 = Ar[2];
        float2 c01 = *(const float2*)&Cr[0];
        float2 c23 = *(const float2*)&Cr[2];
        float2 c45 = *(const float2*)&Cr[4];
        float cv[6] = {c01.x, c01.y, c23.x, c23.y, c45.x, c45.y};
#pragma unroll
        for (int c = 0; c < 6; c++) {
            acc[0][c] -= fabsf(a0 + cv[c]);
            acc[1][c] -= fabsf(a1 + cv[c]);
            acc[2][c] -= fabsf(a2 + cv[c]);
        }
    }

    const size_t tilebase = ((size_t)b * 96 + it * 48) * 96;
    float* P = g_P + (size_t)hs * PSTRIDE + tilebase + (size_t)il * 96 + jl;
#pragma unroll
    for (int r = 0; r < 3; r++) {
#pragma unroll
        for (int c = 0; c < 6; c += 2)
            *(float2*)&P[(size_t)r * 96 + c] = make_float2(acc[r][c], acc[r][c + 1]);
    }

    // ---- arrival counter: last slice block of this (b,it) does CE tail ----
    __threadfence();
    __shared__ int lastflag;
    if (tid == 0) {
        int prev = atomicAdd(&g_ctrT[b * 2 + it], 1);
        lastflag = (prev == NSLICE - 1) ? 1 : 0;
        if (lastflag) g_ctrT[b * 2 + it] = 0;   // reset for next replay
    }
    __syncthreads();
    if (!lastflag) return;
    __threadfence();

    // reuse smem: logits [48][96], vsh[96], ord[96], wpart[8]
    float* lgs  = buf;                       // 4608 floats
    float* vsh  = buf + 4608;                // 96
    int*   ordس = (int*)(buf + 4704);        // 96
    float* wpart = buf + 4800;               // 8

    if (tid < 96)
        vsh[tid] = g_v4[0 * M_ + b * 96 + tid] + g_v4[1 * M_ + b * 96 + tid]
                 + g_v4[2 * M_ + b * 96 + tid] + g_v4[3 * M_ + b * 96 + tid];
    if (tid >= 128 && tid < 224)
        ordس[tid - 128] = order[b * 96 + (tid - 128)];
    __syncthreads();

    // logits = 0.55*v + 0.45 * sum of 8 P slices (fixed order: deterministic)
    for (int t = tid; t < 48 * 96; t += 256) {
        float s = 0.f;
#pragma unroll
        for (int sl = 0; sl < NSLICE; sl++)
            s += g_P[(size_t)sl * PSTRIDE + tilebase + t];
        lgs[t] = 0.45f * s + 0.55f * vsh[t % 96];
    }
    __syncthreads();

    // CE: each warp handles 6 rows of the 48-row tile
    float wsum = 0.f;
#pragma unroll
    for (int rr = 0; rr < 6; rr++) {
        const int lr = warp * 6 + rr;        // local row 0..47
        const int i  = it * 48 + lr;         // row in batch
        float l0 = lgs[lr * 96 + lane];
        float l1 = lgs[lr * 96 + lane + 32];
        float l2 = lgs[lr * 96 + lane + 64];
        float m = fmaxf(l0, fmaxf(l1, l2));
#pragma unroll
        for (int o = 16; o > 0; o >>= 1)
            m = fmaxf(m, __shfl_xor_sync(0xffffffffu, m, o));
        float s = expf(l0 - m) + expf(l1 - m) + expf(l2 - m);
#pragma unroll
        for (int o = 16; o > 0; o >>= 1)
            s += __shfl_xor_sync(0xffffffffu, s, o);
        float lse = m + logf(s);

        int oi = ordس[i];
        int o0 = ordس[lane], o1 = ordس[lane + 32], o2 = ordس[lane + 64];
        unsigned t0 = __ballot_sync(0xffffffffu, o0 == oi + 1);
        unsigned t1 = __ballot_sync(0xffffffffu, o1 == oi + 1);
        unsigned t2 = __ballot_sync(0xffffffffu, o2 == oi + 1);
        int tgt = t0 ? (__ffs(t0) - 1)
                     : (t1 ? (31 + __ffs(t1)) : (t2 ? (63 + __ffs(t2)) : 0));

        int mx = max(o0, max(o1, o2));
#pragma unroll
        for (int o = 16; o > 0; o >>= 1)
            mx = max(mx, __shfl_xor_sync(0xffffffffu, mx, o));
        unsigned M0 = __ballot_sync(0xffffffffu, o0 == mx);
        unsigned M1 = __ballot_sync(0xffffffffu, o1 == mx);
        unsigned M2 = __ballot_sync(0xffffffffu, o2 == mx);
        int last = M0 ? (__ffs(M0) - 1) : (M1 ? (31 + __ffs(M1)) : (63 + __ffs(M2)));

        if (lane == 0)
            wsum += (i == last) ? 0.f : (lse - lgs[lr * 96 + tgt]);
    }
    if (lane == 0) wpart[warp] = wsum;
    __syncthreads();

    // per-tile partial, then global last-block final reduce
    __shared__ int flast;
    if (tid == 0) {
        float ssum = 0.f;
#pragma unroll
        for (int w = 0; w < 8; w++) ssum += wpart[w];
        g_partial[b * 2 + it] = ssum;
        __threadfence();
        int prev = atomicAdd(&g_ctr, 1);
        flast = (prev == NTILE - 1) ? 1 : 0;
    }
    __syncthreads();

    if (flast) {
        __threadfence();
        if (tid < 32) {
            float v = g_partial[tid];
#pragma unroll
            for (int o = 16; o > 0; o >>= 1)
                v += __shfl_xor_sync(0xffffffffu, v, o);
            if (tid == 0) {
                out[0] = v * (1.0f / (16.0f * 95.0f));
                g_ctr = 0;   // reset for next graph replay
            }
        }
    }
}

// ---------------- launcher --------------------------------------------------
extern "C" void kernel_launch(void* const* d_in, const int* in_sizes, int n_in,
                              void* d_out, int out_size) {
    const float* X    = (const float*)d_in[0];
    const float* W1   = (const float*)d_in[1];
    const float* b1   = (const float*)d_in[2];
    const float* W2   = (const float*)d_in[3];
    const int*   order = (const int*)d_in[6];

    static bool attr_set = false;
    if (!attr_set) {
        cudaFuncSetAttribute(gemm_mma_kernel,
                             cudaFuncAttributeMaxDynamicSharedMemorySize, GEMM_SMEM);
        attr_set = true;
    }

    convert_kernel<<<896, 512>>>(X, W1, W2, b1);
    gemm_mma_kernel<<<dim3(8, 12), 256, GEMM_SMEM>>>();
    pairwise_kernel<<<dim3(NSLICE, 2, 16), 256>>>(order, (float*)d_out);
}

// round 13
// speedup vs baseline: 1.1565x; 1.1565x over previous
#include <cuda_runtime.h>
#include <cuda_fp16.h>
#include <cstdint>

#define B_  16
#define L_  96
#define D_  512
#define M_  (B_ * L_)
#define NPART 192
#define PSTRIDE (B_ * L_ * L_)
#define NSLICE 8                        // pairwise h-slices (64 each)

// ---------------- device scratch ------------------------------------------
__device__ float g_AB2[M_ * D_];       // [b][hp][i]: (a+b1)*|w2|, permuted h
__device__ float g_C2[M_ * D_];        // [b][hp][j]: c*|w2|, permuted h
__device__ float g_P[NSLICE * PSTRIDE];
__device__ float g_L[PSTRIDE];         // logits
__device__ float g_v4[4 * M_];         // v partials per GEMM n-block
__device__ float g_partial[NPART];
__device__ float g_b1s[D_];            // b1[h]*|w2[h]| at permuted index
__device__ int   g_Hpos;
__device__ int   g_ctr;                // arrival counter (self-resetting)
__device__ __half g_Xf[M_ * D_];
__device__ __half g_Wt[1024 * D_];     // [n][k], |w2|-scaled, perm rows

// ---------------- helpers ---------------------------------------------------
__device__ __forceinline__ uint32_t smem_u32(const void* p) {
    uint32_t a;
    asm("{ .reg .u64 t; cvta.to.shared.u64 t, %1; cvt.u32.u64 %0, t; }"
        : "=r"(a) : "l"(p));
    return a;
}
__device__ __forceinline__ void ldsm_x4(uint32_t* r, uint32_t addr) {
    asm volatile("ldmatrix.sync.aligned.m8n8.x4.shared.b16 {%0,%1,%2,%3}, [%4];"
                 : "=r"(r[0]), "=r"(r[1]), "=r"(r[2]), "=r"(r[3]) : "r"(addr));
}
__device__ __forceinline__ void mma_f16(float* c, const uint32_t* a,
                                        uint32_t b0, uint32_t b1) {
    asm volatile(
        "mma.sync.aligned.m16n8k16.row.col.f32.f16.f16.f32 "
        "{%0,%1,%2,%3}, {%4,%5,%6,%7}, {%8,%9}, {%0,%1,%2,%3};"
        : "+f"(c[0]), "+f"(c[1]), "+f"(c[2]), "+f"(c[3])
        : "r"(a[0]), "r"(a[1]), "r"(a[2]), "r"(a[3]), "r"(b0), "r"(b1));
}
__device__ __forceinline__ void cp_async16(uint32_t saddr, const void* gaddr) {
    asm volatile("cp.async.cg.shared.global [%0], [%1], 16;"
                 :: "r"(saddr), "l"(gaddr));
}

// ---------------- kernel A: convert (X -> fp16) + (W1 -> scaled/perm T) ----
__global__ void __launch_bounds__(512)
convert_kernel(const float* __restrict__ X, const float* __restrict__ W1,
               const float* __restrict__ W2, const float* __restrict__ b1) {
    const int tid = threadIdx.x;
    const int bx = blockIdx.x;
    if (bx < 384) {
        int idx = bx * 512 + tid;                 // over 196608 float4
        float4 v = ((const float4*)X)[idx];
        ((__half2*)g_Xf)[idx * 2 + 0] = __floats2half2_rn(v.x, v.y);
        ((__half2*)g_Xf)[idx * 2 + 1] = __floats2half2_rn(v.z, v.w);
    } else {
        __shared__ float t[32][33];
        __shared__ int   sperm[512];
        __shared__ float sw2a[512];
        __shared__ int   wcnt[16], wpre[17];

        // inlined deterministic sign-partition of h by sign(w2)
        const int lane = tid & 31, w = tid >> 5;
        float v2 = W2[tid];
        bool pos = (v2 >= 0.f);
        unsigned mset = __ballot_sync(0xffffffffu, pos);
        int lpre = __popc(mset & ((1u << lane) - 1u));
        if (lane == 0) wcnt[w] = __popc(mset);
        __syncthreads();
        if (tid == 0) {
            int s = 0;
#pragma unroll
            for (int k = 0; k < 16; k++) { wpre[k] = s; s += wcnt[k]; }
            wpre[16] = s;
        }
        __syncthreads();
        const int Hp = wpre[16];
        int posrank = wpre[w] + lpre;
        sperm[tid] = pos ? posrank : (Hp + tid - posrank);
        sw2a[tid] = fabsf(v2);
        __syncthreads();

        const int wb = bx - 384;                  // 0..511
        const int p  = wb >> 8;
        const int k0 = ((wb >> 4) & 15) * 32;
        const int n0 = (wb & 15) * 32;
        const int tx = tid & 31, ty = tid >> 5;   // (32,16)

        if (wb == 0 && tid == 0) g_Hpos = Hp;
        if (p == 0 && k0 == 0 && tid < 32) {
            int h = n0 + tid;
            g_b1s[sperm[h]] = b1[h] * sw2a[h];
        }
#pragma unroll
        for (int r = 0; r < 32; r += 16)
            t[ty + r][tx] = W1[(size_t)(p * 512 + k0 + ty + r) * 512 + n0 + tx];
        __syncthreads();
#pragma unroll
        for (int r = 0; r < 32; r += 16) {
            const int h = n0 + ty + r;
            float v = t[tx][ty + r] * sw2a[h];
            size_t o = (size_t)(p * 512 + sperm[h]) * 512 + k0 + tx;
            g_Wt[o] = __float2half_rn(v);
        }
    }
}

// ---------------- kernel B: single-pass fp16 GEMM via mma.sync --------------
#define GASTRIDE 80
#define G_ATILE (128 * GASTRIDE)        // 10240
#define G_STAGE (2 * G_ATILE)           // 20480
#define GEMM_SMEM (3 * G_STAGE)         // 61440

__global__ void __launch_bounds__(256, 1)
gemm_mma_kernel() {
    extern __shared__ char smem[];
    const uint32_t smem_base = smem_u32(smem);
    const int tid = threadIdx.x, wid = tid >> 5, lane = tid & 31;
    const int n0 = blockIdx.x * 128;
    const int m0 = blockIdx.y * 128;
    const int m_off = (wid & 3) * 32;
    const int n_off = (wid >> 2) * 64;

    const __half* srcA = g_Xf + (size_t)m0 * 512;
    const __half* srcB = g_Wt + (size_t)n0 * 512;

    const bool isArow = (tid < 128);
    const __half* prow = isArow ? (srcA + (size_t)tid * 512)
                                : (srcB + (size_t)(tid - 128) * 512);
    const uint32_t pdst = (isArow ? tid * GASTRIDE
                                  : G_ATILE + (tid - 128) * GASTRIDE);

    auto prefetch = [&](int c, int buf) {
        const uint32_t d = smem_base + buf * G_STAGE + pdst;
        const __half* s = prow + c * 32;
#pragma unroll
        for (int q = 0; q < 4; q++)
            cp_async16(d + q * 16, s + q * 8);
    };

    float acc[2][8][4];
#pragma unroll
    for (int i = 0; i < 2; i++)
#pragma unroll
        for (int j = 0; j < 8; j++)
#pragma unroll
            for (int k = 0; k < 4; k++) acc[i][j][k] = 0.f;

    const int grp = lane >> 3, ln8 = lane & 7;
    const int a_row = (grp & 1) * 8 + ln8;
    const int a_kB  = (grp >> 1) * 16;
    const int b_row = ((grp >> 1) & 1) * 8 + ln8;
    const int b_kB  = (grp & 1) * 16;

    prefetch(0, 0);
    asm volatile("cp.async.commit_group;" ::: "memory");
    prefetch(1, 1);
    asm volatile("cp.async.commit_group;" ::: "memory");

    for (int c = 0; c < 16; c++) {
        if (c + 2 < 16) {
            asm volatile("cp.async.wait_group 1;" ::: "memory");
        } else {
            asm volatile("cp.async.wait_group 0;" ::: "memory");
        }
        __syncthreads();
        if (c + 2 < 16) {
            prefetch(c + 2, (c + 2) % 3);
            asm volatile("cp.async.commit_group;" ::: "memory");
        }

        const uint32_t base = smem_base + (c % 3) * G_STAGE;
        const uint32_t Bb = base + G_ATILE;
#pragma unroll
        for (int ks = 0; ks < 2; ks++) {
            const int kB = ks * 32;
            uint32_t a[2][4], b[4][4];
#pragma unroll
            for (int fm = 0; fm < 2; fm++)
                ldsm_x4(a[fm], base + (m_off + fm * 16 + a_row) * GASTRIDE
                                    + kB + a_kB);
#pragma unroll
            for (int fp = 0; fp < 4; fp++)
                ldsm_x4(b[fp], Bb + (n_off + fp * 16 + b_row) * GASTRIDE
                                  + kB + b_kB);
#pragma unroll
            for (int fm = 0; fm < 2; fm++)
#pragma unroll
                for (int fp = 0; fp < 4; fp++) {
                    mma_f16(acc[fm][2 * fp + 0], a[fm], b[fp][0], b[fp][1]);
                    mma_f16(acc[fm][2 * fp + 1], a[fm], b[fp][2], b[fp][3]);
                }
        }
        __syncthreads();
    }

    const bool isA = (n0 < 512);
    const int nbase = isA ? n0 : (n0 - 512);
    const int r0 = lane >> 2, cc = (lane & 3) * 2;

    // ---- C-half blocks: signed column sums -> g_v4 (deterministic) ----
    if (!isA) {
        const int Hpos = g_Hpos;
        float s[4] = {0.f, 0.f, 0.f, 0.f};
#pragma unroll
        for (int fm = 0; fm < 2; fm++)
#pragma unroll
            for (int fn = 0; fn < 8; fn++)
#pragma unroll
                for (int e = 0; e < 2; e++) {
                    const int l = n_off + fn * 8 + cc + e;
                    const float sg = (nbase + l < Hpos) ? 1.f : -1.f;
                    s[fm * 2 + 0] += sg * acc[fm][fn][e];
                    s[fm * 2 + 1] += sg * acc[fm][fn][2 + e];
                }
#pragma unroll
        for (int q = 0; q < 4; q++) {
            s[q] += __shfl_xor_sync(0xffffffffu, s[q], 1);
            s[q] += __shfl_xor_sync(0xffffffffu, s[q], 2);
        }
        float* svv = (float*)smem;
        if (wid < 4 && (lane & 3) == 0) {
            svv[m_off +  0 + r0] = s[0];
            svv[m_off +  8 + r0] = s[1];
            svv[m_off + 16 + r0] = s[2];
            svv[m_off + 24 + r0] = s[3];
        }
        __syncthreads();
        if (wid >= 4 && (lane & 3) == 0) {
            svv[m_off +  0 + r0] += s[0];
            svv[m_off +  8 + r0] += s[1];
            svv[m_off + 16 + r0] += s[2];
            svv[m_off + 24 + r0] += s[3];
        }
        __syncthreads();
        if (tid < 128)
            g_v4[(blockIdx.x - 4) * M_ + m0 + tid] = svv[tid];
    }

    // b1s table for A-half blocks
    float* sb1 = (float*)smem;
    if (isA) {
        if (tid < 128) sb1[tid] = g_b1s[n0 + tid];
        __syncthreads();
    }

    // epilogue: straight write, rows already permuted/scaled via Wt
    float* dstBase = isA ? g_AB2 : g_C2;
#pragma unroll
    for (int fm = 0; fm < 2; fm++) {
        const int mr0 = m0 + m_off + fm * 16 + r0;
        const int mr1 = mr0 + 8;
        const int b0r = mr0 / 96, i0r = mr0 - b0r * 96;
        const int b1r = mr1 / 96, i1r = mr1 - b1r * 96;
#pragma unroll
        for (int fn = 0; fn < 8; fn++) {
            const int lc = n_off + fn * 8 + cc;
            const float* a4 = acc[fm][fn];
#pragma unroll
            for (int e = 0; e < 2; e++) {
                const int l = lc + e;
                const float add = isA ? sb1[l] : 0.f;
                dstBase[((size_t)(b0r * 512 + nbase + l)) * 96 + i0r] = a4[e] + add;
                dstBase[((size_t)(b1r * 512 + nbase + l)) * 96 + i1r] = a4[2 + e] + add;
            }
        }
    }
}

// ---------------- kernel D: pairwise abs-sum (64-h slices) -----------------
// grid (8 h-slices, 2 i-tiles, 16 b); 256 thr = 16(i) x 16(j); 3x6 per thread
__global__ void __launch_bounds__(256)
pairwise_kernel() {
    __shared__ __align__(16) float As[64 * 48];
    __shared__ __align__(16) float Cs[64 * 96];

    const int hs = blockIdx.x;
    const int it = blockIdx.y;
    const int b  = blockIdx.z;
    const int tid = threadIdx.x;
    const int ty = tid >> 4, tx = tid & 15;
    const int il = 3 * ty, jl = 6 * tx;

    const float4* srcA = (const float4*)(g_AB2 +
        ((size_t)(b * 512 + hs * 64)) * 96 + it * 48);
    const float4* srcC = (const float4*)(g_C2 +
        ((size_t)(b * 512 + hs * 64)) * 96);
    float4* dA = (float4*)As;
    float4* dC = (float4*)Cs;
#pragma unroll
    for (int t = tid; t < 768; t += 256) {
        int r = t / 12, q = t - r * 12;
        dA[t] = srcA[r * 24 + q];
    }
#pragma unroll
    for (int t = tid; t < 1536; t += 256)
        dC[t] = srcC[t];
    __syncthreads();

    const int bnd = min(max(g_Hpos - hs * 64, 0), 64);
    float acc[3][6] = {{0.f}};

    int h = 0;
#pragma unroll 4
    for (; h < bnd; h++) {
        const float* Ar = &As[h * 48 + il];
        const float* Cr = &Cs[h * 96 + jl];
        float a0 = Ar[0], a1 = Ar[1], a2 = Ar[2];
        float2 c01 = *(const float2*)&Cr[0];
        float2 c23 = *(const float2*)&Cr[2];
        float2 c45 = *(const float2*)&Cr[4];
        float cv[6] = {c01.x, c01.y, c23.x, c23.y, c45.x, c45.y};
#pragma unroll
        for (int c = 0; c < 6; c++) {
            acc[0][c] += fabsf(a0 + cv[c]);
            acc[1][c] += fabsf(a1 + cv[c]);
            acc[2][c] += fabsf(a2 + cv[c]);
        }
    }
#pragma unroll 4
    for (; h < 64; h++) {
        const float* Ar = &As[h * 48 + il];
        const float* Cr = &Cs[h * 96 + jl];
        float a0 = Ar[0], a1 = Ar[1], a2 = Ar[2];
        float2 c01 = *(const float2*)&Cr[0];
        float2 c23 = *(const float2*)&Cr[2];
        float2 c45 = *(const float2*)&Cr[4];
        float cv[6] = {c01.x, c01.y, c23.x, c23.y, c45.x, c45.y};
#pragma unroll
        for (int c = 0; c < 6; c++) {
            acc[0][c] -= fabsf(a0 + cv[c]);
            acc[1][c] -= fabsf(a1 + cv[c]);
            acc[2][c] -= fabsf(a2 + cv[c]);
        }
    }

    float* P = g_P + (size_t)hs * PSTRIDE +
               ((size_t)b * 96 + it * 48 + il) * 96 + jl;
#pragma unroll
    for (int r = 0; r < 3; r++) {
#pragma unroll
        for (int c = 0; c < 6; c += 2)
            *(float2*)&P[(size_t)r * 96 + c] = make_float2(acc[r][c], acc[r][c + 1]);
    }
}

// ---------------- kernel E1: slice-sum -> logits (pure streaming) ----------
// grid (18, 16), 256 threads; each block: 512 consecutive elements of batch b
__global__ void __launch_bounds__(256)
logits_kernel() {
    __shared__ float vsh[96];
    const int b = blockIdx.y;
    const int tid = threadIdx.x;
    if (tid < 96)
        vsh[tid] = g_v4[0 * M_ + b * 96 + tid] + g_v4[1 * M_ + b * 96 + tid]
                 + g_v4[2 * M_ + b * 96 + tid] + g_v4[3 * M_ + b * 96 + tid];
    __syncthreads();

    const size_t bb = (size_t)b * (96 * 96);
#pragma unroll
    for (int q = 0; q < 2; q++) {
        const int t = blockIdx.x * 512 + q * 256 + tid;
        float s = 0.f;
#pragma unroll
        for (int sl = 0; sl < NSLICE; sl++)
            s += g_P[(size_t)sl * PSTRIDE + bb + t];
        g_L[bb + t] = 0.45f * s + 0.55f * vsh[t % 96];
    }
}

// ---------------- kernel E2: fused softmax-CE + final reduce ----------------
__global__ void ce_kernel(const int* __restrict__ order, float* __restrict__ out) {
    __shared__ int   ord[96];
    __shared__ float rowbuf[8][96];
    __shared__ float wpart[8];
    __shared__ int   slast;

    const int b = blockIdx.y, tid = threadIdx.x;
    const int warp = tid >> 5, lane = tid & 31;
    const int i = blockIdx.x * 8 + warp;

    if (tid < 96) ord[tid] = order[b * 96 + tid];
    __syncthreads();

    const size_t ro = ((size_t)b * 96 + i) * 96;
    float l0 = g_L[ro + lane];
    float l1 = g_L[ro + lane + 32];
    float l2 = g_L[ro + lane + 64];
    rowbuf[warp][lane]      = l0;
    rowbuf[warp][lane + 32] = l1;
    rowbuf[warp][lane + 64] = l2;

    float m = fmaxf(l0, fmaxf(l1, l2));
#pragma unroll
    for (int o = 16; o > 0; o >>= 1)
        m = fmaxf(m, __shfl_xor_sync(0xffffffffu, m, o));
    float s = expf(l0 - m) + expf(l1 - m) + expf(l2 - m);
#pragma unroll
    for (int o = 16; o > 0; o >>= 1)
        s += __shfl_xor_sync(0xffffffffu, s, o);
    float lse = m + logf(s);

    int oi = ord[i];
    int o0 = ord[lane], o1 = ord[lane + 32], o2 = ord[lane + 64];
    unsigned t0 = __ballot_sync(0xffffffffu, o0 == oi + 1);
    unsigned t1 = __ballot_sync(0xffffffffu, o1 == oi + 1);
    unsigned t2 = __ballot_sync(0xffffffffu, o2 == oi + 1);
    int tgt = t0 ? (__ffs(t0) - 1)
                 : (t1 ? (31 + __ffs(t1)) : (t2 ? (63 + __ffs(t2)) : 0));

    int mx = max(o0, max(o1, o2));
#pragma unroll
    for (int o = 16; o > 0; o >>= 1)
        mx = max(mx, __shfl_xor_sync(0xffffffffu, mx, o));
    unsigned M0 = __ballot_sync(0xffffffffu, o0 == mx);
    unsigned M1 = __ballot_sync(0xffffffffu, o1 == mx);
    unsigned M2 = __ballot_sync(0xffffffffu, o2 == mx);
    int last = M0 ? (__ffs(M0) - 1) : (M1 ? (31 + __ffs(M1)) : (63 + __ffs(M2)));

    float contrib = (i == last) ? 0.f : (lse - rowbuf[warp][tgt]);
    if (lane == 0) wpart[warp] = contrib;
    __syncthreads();
    if (tid == 0) {
        float ssum = 0.f;
#pragma unroll
        for (int w = 0; w < 8; w++) ssum += wpart[w];
        g_partial[b * 12 + blockIdx.x] = ssum;
        __threadfence();
        slast = (atomicAdd(&g_ctr, 1) == NPART - 1) ? 1 : 0;
    }
    __syncthreads();

    if (slast) {
        __threadfence();
        __shared__ float wsum[8];
        float v = (tid < NPART) ? g_partial[tid] : 0.f;
#pragma unroll
        for (int o = 16; o > 0; o >>= 1)
            v += __shfl_xor_sync(0xffffffffu, v, o);
        if (lane == 0) wsum[warp] = v;
        __syncthreads();
        if (tid == 0) {
            float ss = 0.f;
#pragma unroll
            for (int k = 0; k < 8; k++) ss += wsum[k];
            out[0] = ss * (1.0f / (16.0f * 95.0f));
            g_ctr = 0;   // reset for next graph replay
        }
    }
}

// ---------------- launcher --------------------------------------------------
extern "C" void kernel_launch(void* const* d_in, const int* in_sizes, int n_in,
                              void* d_out, int out_size) {
    const float* X    = (const float*)d_in[0];
    const float* W1   = (const float*)d_in[1];
    const float* b1   = (const float*)d_in[2];
    const float* W2   = (const float*)d_in[3];
    const int*   order = (const int*)d_in[6];

    static bool attr_set = false;
    if (!attr_set) {
        cudaFuncSetAttribute(gemm_mma_kernel,
                             cudaFuncAttributeMaxDynamicSharedMemorySize, GEMM_SMEM);
        attr_set = true;
    }

    convert_kernel<<<896, 512>>>(X, W1, W2, b1);
    gemm_mma_kernel<<<dim3(8, 12), 256, GEMM_SMEM>>>();
    pairwise_kernel<<<dim3(NSLICE, 2, 16), 256>>>();
    logits_kernel<<<dim3(18, 16), 256>>>();
    ce_kernel<<<dim3(12, 16), 256>>>(order, (float*)d_out);
}

// round 14
// speedup vs baseline: 1.2241x; 1.0585x over previous
#include <cuda_runtime.h>
#include <cuda_fp16.h>
#include <cstdint>

#define B_  16
#define L_  96
#define D_  512
#define M_  (B_ * L_)
#define NPART 192
#define PSTRIDE (B_ * L_ * L_)
#define NSLICE 8                        // pairwise h-slices (64 each)

// ---------------- device scratch ------------------------------------------
__device__ float g_AB2[M_ * D_];       // [b][hp][i]: (a+b1)*|w2|, permuted h
__device__ float g_C2[M_ * D_];        // [b][hp][j]: c*|w2|, permuted h
__device__ float g_P[NSLICE * PSTRIDE];
__device__ float g_v4[4 * M_];         // v partials per GEMM n-block
__device__ float g_partial[NPART];
__device__ float g_b1s[D_];            // b1[h]*|w2[h]| at permuted index
__device__ int   g_Hpos;
__device__ int   g_ctr;                // arrival counter (self-resetting)
__device__ __half g_Xf[M_ * D_];
__device__ __half g_Wt[1024 * D_];     // [n][k], |w2|-scaled, perm rows

// ---------------- helpers ---------------------------------------------------
__device__ __forceinline__ uint32_t smem_u32(const void* p) {
    uint32_t a;
    asm("{ .reg .u64 t; cvta.to.shared.u64 t, %1; cvt.u32.u64 %0, t; }"
        : "=r"(a) : "l"(p));
    return a;
}
__device__ __forceinline__ void ldsm_x4(uint32_t* r, uint32_t addr) {
    asm volatile("ldmatrix.sync.aligned.m8n8.x4.shared.b16 {%0,%1,%2,%3}, [%4];"
                 : "=r"(r[0]), "=r"(r[1]), "=r"(r[2]), "=r"(r[3]) : "r"(addr));
}
__device__ __forceinline__ void mma_f16(float* c, const uint32_t* a,
                                        uint32_t b0, uint32_t b1) {
    asm volatile(
        "mma.sync.aligned.m16n8k16.row.col.f32.f16.f16.f32 "
        "{%0,%1,%2,%3}, {%4,%5,%6,%7}, {%8,%9}, {%0,%1,%2,%3};"
        : "+f"(c[0]), "+f"(c[1]), "+f"(c[2]), "+f"(c[3])
        : "r"(a[0]), "r"(a[1]), "r"(a[2]), "r"(a[3]), "r"(b0), "r"(b1));
}
__device__ __forceinline__ void cp_async16(uint32_t saddr, const void* gaddr) {
    asm volatile("cp.async.cg.shared.global [%0], [%1], 16;"
                 :: "r"(saddr), "l"(gaddr));
}

// ---------------- kernel A: convert (X -> fp16) + (W1 -> scaled/perm T) ----
__global__ void __launch_bounds__(512)
convert_kernel(const float* __restrict__ X, const float* __restrict__ W1,
               const float* __restrict__ W2, const float* __restrict__ b1) {
    const int tid = threadIdx.x;
    const int bx = blockIdx.x;
    if (bx < 384) {
        int idx = bx * 512 + tid;                 // over 196608 float4
        float4 v = ((const float4*)X)[idx];
        ((__half2*)g_Xf)[idx * 2 + 0] = __floats2half2_rn(v.x, v.y);
        ((__half2*)g_Xf)[idx * 2 + 1] = __floats2half2_rn(v.z, v.w);
    } else {
        __shared__ float t[32][33];
        __shared__ int   sperm[512];
        __shared__ float sw2a[512];
        __shared__ int   wcnt[16], wpre[17];

        // inlined deterministic sign-partition of h by sign(w2)
        const int lane = tid & 31, w = tid >> 5;
        float v2 = W2[tid];
        bool pos = (v2 >= 0.f);
        unsigned mset = __ballot_sync(0xffffffffu, pos);
        int lpre = __popc(mset & ((1u << lane) - 1u));
        if (lane == 0) wcnt[w] = __popc(mset);
        __syncthreads();
        if (tid == 0) {
            int s = 0;
#pragma unroll
            for (int k = 0; k < 16; k++) { wpre[k] = s; s += wcnt[k]; }
            wpre[16] = s;
        }
        __syncthreads();
        const int Hp = wpre[16];
        int posrank = wpre[w] + lpre;
        sperm[tid] = pos ? posrank : (Hp + tid - posrank);
        sw2a[tid] = fabsf(v2);
        __syncthreads();

        const int wb = bx - 384;                  // 0..511
        const int p  = wb >> 8;
        const int k0 = ((wb >> 4) & 15) * 32;
        const int n0 = (wb & 15) * 32;
        const int tx = tid & 31, ty = tid >> 5;   // (32,16)

        if (wb == 0 && tid == 0) g_Hpos = Hp;
        if (p == 0 && k0 == 0 && tid < 32) {
            int h = n0 + tid;
            g_b1s[sperm[h]] = b1[h] * sw2a[h];
        }
#pragma unroll
        for (int r = 0; r < 32; r += 16)
            t[ty + r][tx] = W1[(size_t)(p * 512 + k0 + ty + r) * 512 + n0 + tx];
        __syncthreads();
#pragma unroll
        for (int r = 0; r < 32; r += 16) {
            const int h = n0 + ty + r;
            float v = t[tx][ty + r] * sw2a[h];
            size_t o = (size_t)(p * 512 + sperm[h]) * 512 + k0 + tx;
            g_Wt[o] = __float2half_rn(v);
        }
    }
}

// ---------------- kernel B: single-pass fp16 GEMM via mma.sync --------------
#define GASTRIDE 80
#define G_ATILE (128 * GASTRIDE)        // 10240
#define G_STAGE (2 * G_ATILE)           // 20480
#define GEMM_SMEM (3 * G_STAGE)         // 61440

__global__ void __launch_bounds__(256, 1)
gemm_mma_kernel() {
    extern __shared__ char smem[];
    const uint32_t smem_base = smem_u32(smem);
    const int tid = threadIdx.x, wid = tid >> 5, lane = tid & 31;
    const int n0 = blockIdx.x * 128;
    const int m0 = blockIdx.y * 128;
    const int m_off = (wid & 3) * 32;
    const int n_off = (wid >> 2) * 64;

    const __half* srcA = g_Xf + (size_t)m0 * 512;
    const __half* srcB = g_Wt + (size_t)n0 * 512;

    const bool isArow = (tid < 128);
    const __half* prow = isArow ? (srcA + (size_t)tid * 512)
                                : (srcB + (size_t)(tid - 128) * 512);
    const uint32_t pdst = (isArow ? tid * GASTRIDE
                                  : G_ATILE + (tid - 128) * GASTRIDE);

    auto prefetch = [&](int c, int buf) {
        const uint32_t d = smem_base + buf * G_STAGE + pdst;
        const __half* s = prow + c * 32;
#pragma unroll
        for (int q = 0; q < 4; q++)
            cp_async16(d + q * 16, s + q * 8);
    };

    float acc[2][8][4];
#pragma unroll
    for (int i = 0; i < 2; i++)
#pragma unroll
        for (int j = 0; j < 8; j++)
#pragma unroll
            for (int k = 0; k < 4; k++) acc[i][j][k] = 0.f;

    const int grp = lane >> 3, ln8 = lane & 7;
    const int a_row = (grp & 1) * 8 + ln8;
    const int a_kB  = (grp >> 1) * 16;
    const int b_row = ((grp >> 1) & 1) * 8 + ln8;
    const int b_kB  = (grp & 1) * 16;

    prefetch(0, 0);
    asm volatile("cp.async.commit_group;" ::: "memory");
    prefetch(1, 1);
    asm volatile("cp.async.commit_group;" ::: "memory");

    for (int c = 0; c < 16; c++) {
        if (c + 2 < 16) {
            asm volatile("cp.async.wait_group 1;" ::: "memory");
        } else {
            asm volatile("cp.async.wait_group 0;" ::: "memory");
        }
        __syncthreads();
        if (c + 2 < 16) {
            prefetch(c + 2, (c + 2) % 3);
            asm volatile("cp.async.commit_group;" ::: "memory");
        }

        const uint32_t base = smem_base + (c % 3) * G_STAGE;
        const uint32_t Bb = base + G_ATILE;
#pragma unroll
        for (int ks = 0; ks < 2; ks++) {
            const int kB = ks * 32;
            uint32_t a[2][4], b[4][4];
#pragma unroll
            for (int fm = 0; fm < 2; fm++)
                ldsm_x4(a[fm], base + (m_off + fm * 16 + a_row) * GASTRIDE
                                    + kB + a_kB);
#pragma unroll
            for (int fp = 0; fp < 4; fp++)
                ldsm_x4(b[fp], Bb + (n_off + fp * 16 + b_row) * GASTRIDE
                                  + kB + b_kB);
#pragma unroll
            for (int fm = 0; fm < 2; fm++)
#pragma unroll
                for (int fp = 0; fp < 4; fp++) {
                    mma_f16(acc[fm][2 * fp + 0], a[fm], b[fp][0], b[fp][1]);
                    mma_f16(acc[fm][2 * fp + 1], a[fm], b[fp][2], b[fp][3]);
                }
        }
        __syncthreads();
    }

    const bool isA = (n0 < 512);
    const int nbase = isA ? n0 : (n0 - 512);
    const int r0 = lane >> 2, cc = (lane & 3) * 2;

    // ---- C-half blocks: signed column sums -> g_v4 (deterministic) ----
    if (!isA) {
        const int Hpos = g_Hpos;
        float s[4] = {0.f, 0.f, 0.f, 0.f};
#pragma unroll
        for (int fm = 0; fm < 2; fm++)
#pragma unroll
            for (int fn = 0; fn < 8; fn++)
#pragma unroll
                for (int e = 0; e < 2; e++) {
                    const int l = n_off + fn * 8 + cc + e;
                    const float sg = (nbase + l < Hpos) ? 1.f : -1.f;
                    s[fm * 2 + 0] += sg * acc[fm][fn][e];
                    s[fm * 2 + 1] += sg * acc[fm][fn][2 + e];
                }
#pragma unroll
        for (int q = 0; q < 4; q++) {
            s[q] += __shfl_xor_sync(0xffffffffu, s[q], 1);
            s[q] += __shfl_xor_sync(0xffffffffu, s[q], 2);
        }
        float* svv = (float*)smem;
        if (wid < 4 && (lane & 3) == 0) {
            svv[m_off +  0 + r0] = s[0];
            svv[m_off +  8 + r0] = s[1];
            svv[m_off + 16 + r0] = s[2];
            svv[m_off + 24 + r0] = s[3];
        }
        __syncthreads();
        if (wid >= 4 && (lane & 3) == 0) {
            svv[m_off +  0 + r0] += s[0];
            svv[m_off +  8 + r0] += s[1];
            svv[m_off + 16 + r0] += s[2];
            svv[m_off + 24 + r0] += s[3];
        }
        __syncthreads();
        if (tid < 128)
            g_v4[(blockIdx.x - 4) * M_ + m0 + tid] = svv[tid];
    }

    // b1s table for A-half blocks
    float* sb1 = (float*)smem;
    if (isA) {
        if (tid < 128) sb1[tid] = g_b1s[n0 + tid];
        __syncthreads();
    }

    // epilogue: straight write, rows already permuted/scaled via Wt
    float* dstBase = isA ? g_AB2 : g_C2;
#pragma unroll
    for (int fm = 0; fm < 2; fm++) {
        const int mr0 = m0 + m_off + fm * 16 + r0;
        const int mr1 = mr0 + 8;
        const int b0r = mr0 / 96, i0r = mr0 - b0r * 96;
        const int b1r = mr1 / 96, i1r = mr1 - b1r * 96;
#pragma unroll
        for (int fn = 0; fn < 8; fn++) {
            const int lc = n_off + fn * 8 + cc;
            const float* a4 = acc[fm][fn];
#pragma unroll
            for (int e = 0; e < 2; e++) {
                const int l = lc + e;
                const float add = isA ? sb1[l] : 0.f;
                dstBase[((size_t)(b0r * 512 + nbase + l)) * 96 + i0r] = a4[e] + add;
                dstBase[((size_t)(b1r * 512 + nbase + l)) * 96 + i1r] = a4[2 + e] + add;
            }
        }
    }
}

// ---------------- kernel D: pairwise abs-sum (64-h slices) -----------------
// grid (8 h-slices, 2 i-tiles, 16 b); 256 thr = 16(i) x 16(j); 3x6 per thread
__global__ void __launch_bounds__(256)
pairwise_kernel() {
    __shared__ __align__(16) float As[64 * 48];
    __shared__ __align__(16) float Cs[64 * 96];

    const int hs = blockIdx.x;
    const int it = blockIdx.y;
    const int b  = blockIdx.z;
    const int tid = threadIdx.x;
    const int ty = tid >> 4, tx = tid & 15;
    const int il = 3 * ty, jl = 6 * tx;

    const float4* srcA = (const float4*)(g_AB2 +
        ((size_t)(b * 512 + hs * 64)) * 96 + it * 48);
    const float4* srcC = (const float4*)(g_C2 +
        ((size_t)(b * 512 + hs * 64)) * 96);
    float4* dA = (float4*)As;
    float4* dC = (float4*)Cs;
#pragma unroll
    for (int t = tid; t < 768; t += 256) {
        int r = t / 12, q = t - r * 12;
        dA[t] = srcA[r * 24 + q];
    }
#pragma unroll
    for (int t = tid; t < 1536; t += 256)
        dC[t] = srcC[t];
    __syncthreads();

    const int bnd = min(max(g_Hpos - hs * 64, 0), 64);
    float acc[3][6] = {{0.f}};

    int h = 0;
#pragma unroll 4
    for (; h < bnd; h++) {
        const float* Ar = &As[h * 48 + il];
        const float* Cr = &Cs[h * 96 + jl];
        float a0 = Ar[0], a1 = Ar[1], a2 = Ar[2];
        float2 c01 = *(const float2*)&Cr[0];
        float2 c23 = *(const float2*)&Cr[2];
        float2 c45 = *(const float2*)&Cr[4];
        float cv[6] = {c01.x, c01.y, c23.x, c23.y, c45.x, c45.y};
#pragma unroll
        for (int c = 0; c < 6; c++) {
            acc[0][c] += fabsf(a0 + cv[c]);
            acc[1][c] += fabsf(a1 + cv[c]);
            acc[2][c] += fabsf(a2 + cv[c]);
        }
    }
#pragma unroll 4
    for (; h < 64; h++) {
        const float* Ar = &As[h * 48 + il];
        const float* Cr = &Cs[h * 96 + jl];
        float a0 = Ar[0], a1 = Ar[1], a2 = Ar[2];
        float2 c01 = *(const float2*)&Cr[0];
        float2 c23 = *(const float2*)&Cr[2];
        float2 c45 = *(const float2*)&Cr[4];
        float cv[6] = {c01.x, c01.y, c23.x, c23.y, c45.x, c45.y};
#pragma unroll
        for (int c = 0; c < 6; c++) {
            acc[0][c] -= fabsf(a0 + cv[c]);
            acc[1][c] -= fabsf(a1 + cv[c]);
            acc[2][c] -= fabsf(a2 + cv[c]);
        }
    }

    float* P = g_P + (size_t)hs * PSTRIDE +
               ((size_t)b * 96 + it * 48 + il) * 96 + jl;
#pragma unroll
    for (int r = 0; r < 3; r++) {
#pragma unroll
        for (int c = 0; c < 6; c += 2)
            *(float2*)&P[(size_t)r * 96 + c] = make_float2(acc[r][c], acc[r][c + 1]);
    }
}

// ---------------- kernel E: staged logits + softmax-CE + final reduce ------
// grid (12, 16): block handles 8 rows of batch b. 192 threads stage logits
// via float4 slice-sums (coalesced, MLP=8), then 8 warps do CE on 8 rows.
__global__ void __launch_bounds__(256)
ce_kernel(const int* __restrict__ order, float* __restrict__ out) {
    __shared__ __align__(16) float lgs[8 * 96];
    __shared__ float vsh[96];
    __shared__ int   ord[96];
    __shared__ float wpart[8];
    __shared__ int   slast;

    const int b = blockIdx.y, tid = threadIdx.x;
    const int warp = tid >> 5, lane = tid & 31;
    const int i0 = blockIdx.x * 8;

    if (tid < 96)
        vsh[tid] = g_v4[0 * M_ + b * 96 + tid] + g_v4[1 * M_ + b * 96 + tid]
                 + g_v4[2 * M_ + b * 96 + tid] + g_v4[3 * M_ + b * 96 + tid];
    if (tid >= 128 && tid < 224)
        ord[tid - 128] = order[b * 96 + (tid - 128)];
    __syncthreads();

    // stage logits: 8 rows x 24 float4 = 192 threads, 8 slice-loads each
    if (tid < 192) {
        const int lr = tid / 24;          // local row 0..7
        const int j4 = tid % 24;          // float4 column
        const size_t base = (((size_t)b * 96 + i0 + lr) * 96) / 4 + j4;
        const float4* P4 = (const float4*)g_P;
        float4 s = make_float4(0.f, 0.f, 0.f, 0.f);
#pragma unroll
        for (int sl = 0; sl < NSLICE; sl++) {
            float4 p = P4[(size_t)sl * (PSTRIDE / 4) + base];
            s.x += p.x; s.y += p.y; s.z += p.z; s.w += p.w;
        }
        const int j = j4 * 4;
        float4 r;
        r.x = 0.45f * s.x + 0.55f * vsh[j + 0];
        r.y = 0.45f * s.y + 0.55f * vsh[j + 1];
        r.z = 0.45f * s.z + 0.55f * vsh[j + 2];
        r.w = 0.45f * s.w + 0.55f * vsh[j + 3];
        *(float4*)&lgs[lr * 96 + j] = r;
    }
    __syncthreads();

    // CE: warp handles row i0+warp
    const int i = i0 + warp;
    float l0 = lgs[warp * 96 + lane];
    float l1 = lgs[warp * 96 + lane + 32];
    float l2 = lgs[warp * 96 + lane + 64];

    float m = fmaxf(l0, fmaxf(l1, l2));
#pragma unroll
    for (int o = 16; o > 0; o >>= 1)
        m = fmaxf(m, __shfl_xor_sync(0xffffffffu, m, o));
    float s = expf(l0 - m) + expf(l1 - m) + expf(l2 - m);
#pragma unroll
    for (int o = 16; o > 0; o >>= 1)
        s += __shfl_xor_sync(0xffffffffu, s, o);
    float lse = m + logf(s);

    int oi = ord[i];
    int o0 = ord[lane], o1 = ord[lane + 32], o2 = ord[lane + 64];
    unsigned t0 = __ballot_sync(0xffffffffu, o0 == oi + 1);
    unsigned t1 = __ballot_sync(0xffffffffu, o1 == oi + 1);
    unsigned t2 = __ballot_sync(0xffffffffu, o2 == oi + 1);
    int tgt = t0 ? (__ffs(t0) - 1)
                 : (t1 ? (31 + __ffs(t1)) : (t2 ? (63 + __ffs(t2)) : 0));

    int mx = max(o0, max(o1, o2));
#pragma unroll
    for (int o = 16; o > 0; o >>= 1)
        mx = max(mx, __shfl_xor_sync(0xffffffffu, mx, o));
    unsigned M0 = __ballot_sync(0xffffffffu, o0 == mx);
    unsigned M1 = __ballot_sync(0xffffffffu, o1 == mx);
    unsigned M2 = __ballot_sync(0xffffffffu, o2 == mx);
    int last = M0 ? (__ffs(M0) - 1) : (M1 ? (31 + __ffs(M1)) : (63 + __ffs(M2)));

    float contrib = (i == last) ? 0.f : (lse - lgs[warp * 96 + tgt]);
    if (lane == 0) wpart[warp] = contrib;
    __syncthreads();
    if (tid == 0) {
        float ssum = 0.f;
#pragma unroll
        for (int w = 0; w < 8; w++) ssum += wpart[w];
        g_partial[b * 12 + blockIdx.x] = ssum;
        __threadfence();
        slast = (atomicAdd(&g_ctr, 1) == NPART - 1) ? 1 : 0;
    }
    __syncthreads();

    if (slast) {
        __threadfence();
        __shared__ float wsum[8];
        float v = (tid < NPART) ? g_partial[tid] : 0.f;
#pragma unroll
        for (int o = 16; o > 0; o >>= 1)
            v += __shfl_xor_sync(0xffffffffu, v, o);
        if (lane == 0) wsum[warp] = v;
        __syncthreads();
        if (tid == 0) {
            float ss = 0.f;
#pragma unroll
            for (int k = 0; k < 8; k++) ss += wsum[k];
            out[0] = ss * (1.0f / (16.0f * 95.0f));
            g_ctr = 0;   // reset for next graph replay
        }
    }
}

// ---------------- launcher --------------------------------------------------
extern "C" void kernel_launch(void* const* d_in, const int* in_sizes, int n_in,
                              void* d_out, int out_size) {
    const float* X    = (const float*)d_in[0];
    const float* W1   = (const float*)d_in[1];
    const float* b1   = (const float*)d_in[2];
    const float* W2   = (const float*)d_in[3];
    const int*   order = (const int*)d_in[6];

    static bool attr_set = false;
    if (!attr_set) {
        cudaFuncSetAttribute(gemm_mma_kernel,
                             cudaFuncAttributeMaxDynamicSharedMemorySize, GEMM_SMEM);
        attr_set = true;
    }

    convert_kernel<<<896, 512>>>(X, W1, W2, b1);
    gemm_mma_kernel<<<dim3(8, 12), 256, GEMM_SMEM>>>();
    pairwise_kernel<<<dim3(NSLICE, 2, 16), 256>>>();
    ce_kernel<<<dim3(12, 16), 256>>>(order, (float*)d_out);
}

// round 15
// speedup vs baseline: 1.3039x; 1.0652x over previous
#include <cuda_runtime.h>
#include <cuda_fp16.h>
#include <cstdint>

#define B_  16
#define L_  96
#define D_  512
#define M_  (B_ * L_)
#define NPART 384
#define PSTRIDE (B_ * L_ * L_)
#define NSLICE 8                        // pairwise h-slices (64 each)

// ---------------- device scratch ------------------------------------------
__device__ float g_AB2[M_ * D_];       // [b][hp][i]: (a+b1)*|w2|, permuted h
__device__ float g_C2[M_ * D_];        // [b][hp][j]: c*|w2|, permuted h
__device__ float g_P[NSLICE * PSTRIDE];
__device__ float g_v4[4 * M_];         // v partials per GEMM n-block
__device__ float g_partial[NPART];
__device__ float g_b1s[D_];            // b1[h]*|w2[h]| at permuted index
__device__ int   g_Hpos;
__device__ int   g_ctr;                // arrival counter (self-resetting)
__device__ __half g_Xf[M_ * D_];
__device__ __half g_Wt[1024 * D_];     // [n][k], |w2|-scaled, perm rows

// ---------------- helpers ---------------------------------------------------
__device__ __forceinline__ uint32_t smem_u32(const void* p) {
    uint32_t a;
    asm("{ .reg .u64 t; cvta.to.shared.u64 t, %1; cvt.u32.u64 %0, t; }"
        : "=r"(a) : "l"(p));
    return a;
}
__device__ __forceinline__ void ldsm_x4(uint32_t* r, uint32_t addr) {
    asm volatile("ldmatrix.sync.aligned.m8n8.x4.shared.b16 {%0,%1,%2,%3}, [%4];"
                 : "=r"(r[0]), "=r"(r[1]), "=r"(r[2]), "=r"(r[3]) : "r"(addr));
}
__device__ __forceinline__ void mma_f16(float* c, const uint32_t* a,
                                        uint32_t b0, uint32_t b1) {
    asm volatile(
        "mma.sync.aligned.m16n8k16.row.col.f32.f16.f16.f32 "
        "{%0,%1,%2,%3}, {%4,%5,%6,%7}, {%8,%9}, {%0,%1,%2,%3};"
        : "+f"(c[0]), "+f"(c[1]), "+f"(c[2]), "+f"(c[3])
        : "r"(a[0]), "r"(a[1]), "r"(a[2]), "r"(a[3]), "r"(b0), "r"(b1));
}
__device__ __forceinline__ void cp_async16(uint32_t saddr, const void* gaddr) {
    asm volatile("cp.async.cg.shared.global [%0], [%1], 16;"
                 :: "r"(saddr), "l"(gaddr));
}

// ---------------- kernel A: convert (X -> fp16) + (W1 -> scaled/perm T) ----
// blocks [0,96): X split (4 float4/thread). blocks [96,608): W1 T+scale+perm.
__global__ void __launch_bounds__(512)
convert_kernel(const float* __restrict__ X, const float* __restrict__ W1,
               const float* __restrict__ W2, const float* __restrict__ b1) {
    const int tid = threadIdx.x;
    const int bx = blockIdx.x;
    if (bx < 96) {
#pragma unroll
        for (int q = 0; q < 4; q++) {
            int idx = bx * 2048 + q * 512 + tid;   // over 196608 float4
            float4 v = ((const float4*)X)[idx];
            ((__half2*)g_Xf)[idx * 2 + 0] = __floats2half2_rn(v.x, v.y);
            ((__half2*)g_Xf)[idx * 2 + 1] = __floats2half2_rn(v.z, v.w);
        }
    } else {
        __shared__ float t[32][33];
        __shared__ int   sperm[512];
        __shared__ float sw2a[512];
        __shared__ int   wcnt[16], wpre[17];

        // inlined deterministic sign-partition of h by sign(w2)
        const int lane = tid & 31, w = tid >> 5;
        float v2 = W2[tid];
        bool pos = (v2 >= 0.f);
        unsigned mset = __ballot_sync(0xffffffffu, pos);
        int lpre = __popc(mset & ((1u << lane) - 1u));
        if (lane == 0) wcnt[w] = __popc(mset);
        __syncthreads();
        if (tid == 0) {
            int s = 0;
#pragma unroll
            for (int k = 0; k < 16; k++) { wpre[k] = s; s += wcnt[k]; }
            wpre[16] = s;
        }
        __syncthreads();
        const int Hp = wpre[16];
        int posrank = wpre[w] + lpre;
        sperm[tid] = pos ? posrank : (Hp + tid - posrank);
        sw2a[tid] = fabsf(v2);
        __syncthreads();

        const int wb = bx - 96;                   // 0..511
        const int p  = wb >> 8;
        const int k0 = ((wb >> 4) & 15) * 32;
        const int n0 = (wb & 15) * 32;
        const int tx = tid & 31, ty = tid >> 5;   // (32,16)

        if (wb == 0 && tid == 0) g_Hpos = Hp;
        if (p == 0 && k0 == 0 && tid < 32) {
            int h = n0 + tid;
            g_b1s[sperm[h]] = b1[h] * sw2a[h];
        }
#pragma unroll
        for (int r = 0; r < 32; r += 16)
            t[ty + r][tx] = W1[(size_t)(p * 512 + k0 + ty + r) * 512 + n0 + tx];
        __syncthreads();
#pragma unroll
        for (int r = 0; r < 32; r += 16) {
            const int h = n0 + ty + r;
            float v = t[tx][ty + r] * sw2a[h];
            size_t o = (size_t)(p * 512 + sperm[h]) * 512 + k0 + tx;
            g_Wt[o] = __float2half_rn(v);
        }
    }
}

// ---------------- kernel B: fp16 GEMM, 192 blocks, tile 64m x 128n ---------
#define GASTRIDE 80
#define G_ATILE (64 * GASTRIDE)         // 5120
#define G_STAGE ((64 + 128) * GASTRIDE) // 15360
#define GEMM_SMEM (3 * G_STAGE)         // 46080

__global__ void __launch_bounds__(256)
gemm_mma_kernel() {
    extern __shared__ char smem[];
    const uint32_t smem_base = smem_u32(smem);
    const int tid = threadIdx.x, wid = tid >> 5, lane = tid & 31;
    const int n0 = blockIdx.x * 128;       // 0..896
    const int m0 = blockIdx.y * 64;        // 0..1472
    const int m_off  = (wid & 1) * 32;     // 2 m-warps
    const int n_woff = (wid >> 1) * 32;    // 4 n-warps

    const __half* srcA = g_Xf + (size_t)m0 * 512;
    const __half* srcB = g_Wt + (size_t)n0 * 512;

    // per-thread prefetch: 3 x 16B segments per stage (192 rows x 4 segs / 256)
    const __half* pr_[3];
    uint32_t      pd_[3];
#pragma unroll
    for (int it = 0; it < 3; it++) {
        const int t = it * 256 + tid;
        const int row = t >> 2, q = t & 3;
        pr_[it] = (row < 64) ? (srcA + (size_t)row * 512 + q * 8)
                             : (srcB + (size_t)(row - 64) * 512 + q * 8);
        pd_[it] = row * GASTRIDE + q * 16;  // row 64 lands exactly at G_ATILE
    }
    auto prefetch = [&](int c, int buf) {
        const uint32_t d = smem_base + buf * G_STAGE;
#pragma unroll
        for (int it = 0; it < 3; it++)
            cp_async16(d + pd_[it], pr_[it] + c * 32);
    };

    float acc[2][4][4];
#pragma unroll
    for (int i = 0; i < 2; i++)
#pragma unroll
        for (int j = 0; j < 4; j++)
#pragma unroll
            for (int k = 0; k < 4; k++) acc[i][j][k] = 0.f;

    const int grp = lane >> 3, ln8 = lane & 7;
    const int a_row = (grp & 1) * 8 + ln8;
    const int a_kB  = (grp >> 1) * 16;
    const int b_row = ((grp >> 1) & 1) * 8 + ln8;
    const int b_kB  = (grp & 1) * 16;

    prefetch(0, 0);
    asm volatile("cp.async.commit_group;" ::: "memory");
    prefetch(1, 1);
    asm volatile("cp.async.commit_group;" ::: "memory");

    for (int c = 0; c < 16; c++) {
        if (c + 2 < 16) {
            asm volatile("cp.async.wait_group 1;" ::: "memory");
        } else {
            asm volatile("cp.async.wait_group 0;" ::: "memory");
        }
        __syncthreads();
        if (c + 2 < 16) {
            prefetch(c + 2, (c + 2) % 3);
            asm volatile("cp.async.commit_group;" ::: "memory");
        }

        const uint32_t base = smem_base + (c % 3) * G_STAGE;
        const uint32_t Bb = base + G_ATILE;
#pragma unroll
        for (int ks = 0; ks < 2; ks++) {
            const int kB = ks * 32;
            uint32_t a[2][4], b[2][4];
#pragma unroll
            for (int fm = 0; fm < 2; fm++)
                ldsm_x4(a[fm], base + (m_off + fm * 16 + a_row) * GASTRIDE
                                    + kB + a_kB);
#pragma unroll
            for (int fp = 0; fp < 2; fp++)
                ldsm_x4(b[fp], Bb + (n_woff + fp * 16 + b_row) * GASTRIDE
                                  + kB + b_kB);
#pragma unroll
            for (int fm = 0; fm < 2; fm++)
#pragma unroll
                for (int fp = 0; fp < 2; fp++) {
                    mma_f16(acc[fm][2 * fp + 0], a[fm], b[fp][0], b[fp][1]);
                    mma_f16(acc[fm][2 * fp + 1], a[fm], b[fp][2], b[fp][3]);
                }
        }
        __syncthreads();
    }

    const bool isA = (n0 < 512);
    const int nbase = isA ? n0 : (n0 - 512);
    const int r0 = lane >> 2, cc = (lane & 3) * 2;

    // ---- C-half blocks: signed column sums -> g_v4 (deterministic) ----
    if (!isA) {
        const int Hpos = g_Hpos;
        float s[4] = {0.f, 0.f, 0.f, 0.f};
#pragma unroll
        for (int fm = 0; fm < 2; fm++)
#pragma unroll
            for (int fn = 0; fn < 4; fn++)
#pragma unroll
                for (int e = 0; e < 2; e++) {
                    const int l = n_woff + fn * 8 + cc + e;
                    const float sg = (nbase + l < Hpos) ? 1.f : -1.f;
                    s[fm * 2 + 0] += sg * acc[fm][fn][e];
                    s[fm * 2 + 1] += sg * acc[fm][fn][2 + e];
                }
#pragma unroll
        for (int q = 0; q < 4; q++) {
            s[q] += __shfl_xor_sync(0xffffffffu, s[q], 1);
            s[q] += __shfl_xor_sync(0xffffffffu, s[q], 2);
        }
        float* svv = (float*)smem;          // [4 n-warps][64 rows]
        if ((lane & 3) == 0) {
            const int nw = wid >> 1;
            svv[nw * 64 + m_off +  0 + r0] = s[0];
            svv[nw * 64 + m_off +  8 + r0] = s[1];
            svv[nw * 64 + m_off + 16 + r0] = s[2];
            svv[nw * 64 + m_off + 24 + r0] = s[3];
        }
        __syncthreads();
        if (tid < 64)
            g_v4[(blockIdx.x - 4) * M_ + m0 + tid] =
                svv[tid] + svv[64 + tid] + svv[128 + tid] + svv[192 + tid];
    }

    // b1s table for A-half blocks
    float* sb1 = (float*)smem;
    if (isA) {
        __syncthreads();
        if (tid < 128) sb1[tid] = g_b1s[n0 + tid];
        __syncthreads();
    }

    // epilogue: straight write, rows already permuted/scaled via Wt
    float* dstBase = isA ? g_AB2 : g_C2;
#pragma unroll
    for (int fm = 0; fm < 2; fm++) {
        const int mr0 = m0 + m_off + fm * 16 + r0;
        const int mr1 = mr0 + 8;
        const int b0r = mr0 / 96, i0r = mr0 - b0r * 96;
        const int b1r = mr1 / 96, i1r = mr1 - b1r * 96;
#pragma unroll
        for (int fn = 0; fn < 4; fn++) {
            const int lc = n_woff + fn * 8 + cc;
            const float* a4 = acc[fm][fn];
#pragma unroll
            for (int e = 0; e < 2; e++) {
                const int l = lc + e;
                const float add = isA ? sb1[l] : 0.f;
                dstBase[((size_t)(b0r * 512 + nbase + l)) * 96 + i0r] = a4[e] + add;
                dstBase[((size_t)(b1r * 512 + nbase + l)) * 96 + i1r] = a4[2 + e] + add;
            }
        }
    }
}

// ---------------- kernel D: pairwise abs-sum (64-h slices) -----------------
// grid (8 h-slices, 2 i-tiles, 16 b); 256 thr = 16(i) x 16(j); 3x6 per thread
__global__ void __launch_bounds__(256)
pairwise_kernel() {
    __shared__ __align__(16) float As[64 * 48];
    __shared__ __align__(16) float Cs[64 * 96];

    const int hs = blockIdx.x;
    const int it = blockIdx.y;
    const int b  = blockIdx.z;
    const int tid = threadIdx.x;
    const int ty = tid >> 4, tx = tid & 15;
    const int il = 3 * ty, jl = 6 * tx;

    const float4* srcA = (const float4*)(g_AB2 +
        ((size_t)(b * 512 + hs * 64)) * 96 + it * 48);
    const float4* srcC = (const float4*)(g_C2 +
        ((size_t)(b * 512 + hs * 64)) * 96);
    float4* dA = (float4*)As;
    float4* dC = (float4*)Cs;
#pragma unroll
    for (int t = tid; t < 768; t += 256) {
        int r = t / 12, q = t - r * 12;
        dA[t] = srcA[r * 24 + q];
    }
#pragma unroll
    for (int t = tid; t < 1536; t += 256)
        dC[t] = srcC[t];
    __syncthreads();

    const int bnd = min(max(g_Hpos - hs * 64, 0), 64);
    float acc[3][6] = {{0.f}};

    int h = 0;
#pragma unroll 4
    for (; h < bnd; h++) {
        const float* Ar = &As[h * 48 + il];
        const float* Cr = &Cs[h * 96 + jl];
        float a0 = Ar[0], a1 = Ar[1], a2 = Ar[2];
        float2 c01 = *(const float2*)&Cr[0];
        float2 c23 = *(const float2*)&Cr[2];
        float2 c45 = *(const float2*)&Cr[4];
        float cv[6] = {c01.x, c01.y, c23.x, c23.y, c45.x, c45.y};
#pragma unroll
        for (int c = 0; c < 6; c++) {
            acc[0][c] += fabsf(a0 + cv[c]);
            acc[1][c] += fabsf(a1 + cv[c]);
            acc[2][c] += fabsf(a2 + cv[c]);
        }
    }
#pragma unroll 4
    for (; h < 64; h++) {
        const float* Ar = &As[h * 48 + il];
        const float* Cr = &Cs[h * 96 + jl];
        float a0 = Ar[0], a1 = Ar[1], a2 = Ar[2];
        float2 c01 = *(const float2*)&Cr[0];
        float2 c23 = *(const float2*)&Cr[2];
        float2 c45 = *(const float2*)&Cr[4];
        float cv[6] = {c01.x, c01.y, c23.x, c23.y, c45.x, c45.y};
#pragma unroll
        for (int c = 0; c < 6; c++) {
            acc[0][c] -= fabsf(a0 + cv[c]);
            acc[1][c] -= fabsf(a1 + cv[c]);
            acc[2][c] -= fabsf(a2 + cv[c]);
        }
    }

    float* P = g_P + (size_t)hs * PSTRIDE +
               ((size_t)b * 96 + it * 48 + il) * 96 + jl;
#pragma unroll
    for (int r = 0; r < 3; r++) {
#pragma unroll
        for (int c = 0; c < 6; c += 2)
            *(float2*)&P[(size_t)r * 96 + c] = make_float2(acc[r][c], acc[r][c + 1]);
    }
}

// ---------------- kernel E: staged logits + softmax-CE + final reduce ------
// grid (24, 16): block = 4 rows of batch b, 128 threads (4 warps).
__global__ void __launch_bounds__(128)
ce_kernel(const int* __restrict__ order, float* __restrict__ out) {
    __shared__ __align__(16) float lgs[4 * 96];
    __shared__ float vsh[96];
    __shared__ int   ord[96];
    __shared__ float wpart[4];
    __shared__ int   slast;

    const int b = blockIdx.y, tid = threadIdx.x;
    const int warp = tid >> 5, lane = tid & 31;
    const int i0 = blockIdx.x * 4;

    if (tid < 96) {
        vsh[tid] = g_v4[0 * M_ + b * 96 + tid] + g_v4[1 * M_ + b * 96 + tid]
                 + g_v4[2 * M_ + b * 96 + tid] + g_v4[3 * M_ + b * 96 + tid];
        ord[tid] = order[b * 96 + tid];
    }
    __syncthreads();

    // stage logits: 4 rows x 24 float4 = 96 threads, 8 slice-loads each
    if (tid < 96) {
        const int lr = tid / 24;          // local row 0..3
        const int j4 = tid % 24;          // float4 column
        const size_t base = (((size_t)b * 96 + i0 + lr) * 96) / 4 + j4;
        const float4* P4 = (const float4*)g_P;
        float4 s = make_float4(0.f, 0.f, 0.f, 0.f);
#pragma unroll
        for (int sl = 0; sl < NSLICE; sl++) {
            float4 p = P4[(size_t)sl * (PSTRIDE / 4) + base];
            s.x += p.x; s.y += p.y; s.z += p.z; s.w += p.w;
        }
        const int j = j4 * 4;
        float4 r;
        r.x = 0.45f * s.x + 0.55f * vsh[j + 0];
        r.y = 0.45f * s.y + 0.55f * vsh[j + 1];
        r.z = 0.45f * s.z + 0.55f * vsh[j + 2];
        r.w = 0.45f * s.w + 0.55f * vsh[j + 3];
        *(float4*)&lgs[lr * 96 + j] = r;
    }
    __syncthreads();

    // CE: warp handles row i0+warp
    const int i = i0 + warp;
    float l0 = lgs[warp * 96 + lane];
    float l1 = lgs[warp * 96 + lane + 32];
    float l2 = lgs[warp * 96 + lane + 64];

    float m = fmaxf(l0, fmaxf(l1, l2));
#pragma unroll
    for (int o = 16; o > 0; o >>= 1)
        m = fmaxf(m, __shfl_xor_sync(0xffffffffu, m, o));
    float s = expf(l0 - m) + expf(l1 - m) + expf(l2 - m);
#pragma unroll
    for (int o = 16; o > 0; o >>= 1)
        s += __shfl_xor_sync(0xffffffffu, s, o);
    float lse = m + logf(s);

    int oi = ord[i];
    int o0 = ord[lane], o1 = ord[lane + 32], o2 = ord[lane + 64];
    unsigned t0 = __ballot_sync(0xffffffffu, o0 == oi + 1);
    unsigned t1 = __ballot_sync(0xffffffffu, o1 == oi + 1);
    unsigned t2 = __ballot_sync(0xffffffffu, o2 == oi + 1);
    int tgt = t0 ? (__ffs(t0) - 1)
                 : (t1 ? (31 + __ffs(t1)) : (t2 ? (63 + __ffs(t2)) : 0));

    int mx = max(o0, max(o1, o2));
#pragma unroll
    for (int o = 16; o > 0; o >>= 1)
        mx = max(mx, __shfl_xor_sync(0xffffffffu, mx, o));
    unsigned M0 = __ballot_sync(0xffffffffu, o0 == mx);
    unsigned M1 = __ballot_sync(0xffffffffu, o1 == mx);
    unsigned M2 = __ballot_sync(0xffffffffu, o2 == mx);
    int last = M0 ? (__ffs(M0) - 1) : (M1 ? (31 + __ffs(M1)) : (63 + __ffs(M2)));

    float contrib = (i == last) ? 0.f : (lse - lgs[warp * 96 + tgt]);
    if (lane == 0) wpart[warp] = contrib;
    __syncthreads();
    if (tid == 0) {
        g_partial[b * 24 + blockIdx.x] = wpart[0] + wpart[1] + wpart[2] + wpart[3];
        __threadfence();
        slast = (atomicAdd(&g_ctr, 1) == NPART - 1) ? 1 : 0;
    }
    __syncthreads();

    if (slast) {
        __threadfence();
        __shared__ float wsum[4];
        float v = g_partial[tid] + g_partial[tid + 128] + g_partial[tid + 256];
#pragma unroll
        for (int o = 16; o > 0; o >>= 1)
            v += __shfl_xor_sync(0xffffffffu, v, o);
        if (lane == 0) wsum[warp] = v;
        __syncthreads();
        if (tid == 0) {
            out[0] = (wsum[0] + wsum[1] + wsum[2] + wsum[3])
                     * (1.0f / (16.0f * 95.0f));
            g_ctr = 0;   // reset for next graph replay
        }
    }
}

// ---------------- launcher --------------------------------------------------
extern "C" void kernel_launch(void* const* d_in, const int* in_sizes, int n_in,
                              void* d_out, int out_size) {
    const float* X    = (const float*)d_in[0];
    const float* W1   = (const float*)d_in[1];
    const float* b1   = (const float*)d_in[2];
    const float* W2   = (const float*)d_in[3];
    const int*   order = (const int*)d_in[6];

    static bool attr_set = false;
    if (!attr_set) {
        cudaFuncSetAttribute(gemm_mma_kernel,
                             cudaFuncAttributeMaxDynamicSharedMemorySize, GEMM_SMEM);
        attr_set = true;
    }

    convert_kernel<<<608, 512>>>(X, W1, W2, b1);
    gemm_mma_kernel<<<dim3(8, 24), 256, GEMM_SMEM>>>();
    pairwise_kernel<<<dim3(NSLICE, 2, 16), 256>>>();
    ce_kernel<<<dim3(24, 16), 128>>>(order, (float*)d_out);
}

// round 16
// speedup vs baseline: 1.3821x; 1.0600x over previous
#include <cuda_runtime.h>
#include <cuda_fp16.h>
#include <cstdint>

#define B_  16
#define L_  96
#define D_  512
#define M_  (B_ * L_)
#define NPART 384
#define PSTRIDE (B_ * L_ * L_)
#define NSLICE 8                        // pairwise h-slices (64 each)

// ---------------- device scratch ------------------------------------------
__device__ float g_AB2[M_ * D_];       // [b][hp][i]: (a+b1)*|w2|, permuted h
__device__ float g_C2[M_ * D_];        // [b][hp][j]: c*|w2|, permuted h
__device__ float g_P[NSLICE * PSTRIDE];
__device__ float g_v4[4 * M_];         // v partials per GEMM n-block
__device__ float g_partial[NPART];
__device__ float g_b1s[D_];            // b1[h]*|w2[h]| at permuted index
__device__ int   g_Hpos;
__device__ __half g_Xf[M_ * D_];
__device__ __half g_Wt[1024 * D_];     // [n][k], |w2|-scaled, perm rows

// ---------------- helpers ---------------------------------------------------
__device__ __forceinline__ uint32_t smem_u32(const void* p) {
    uint32_t a;
    asm("{ .reg .u64 t; cvta.to.shared.u64 t, %1; cvt.u32.u64 %0, t; }"
        : "=r"(a) : "l"(p));
    return a;
}
__device__ __forceinline__ void ldsm_x4(uint32_t* r, uint32_t addr) {
    asm volatile("ldmatrix.sync.aligned.m8n8.x4.shared.b16 {%0,%1,%2,%3}, [%4];"
                 : "=r"(r[0]), "=r"(r[1]), "=r"(r[2]), "=r"(r[3]) : "r"(addr));
}
__device__ __forceinline__ void mma_f16(float* c, const uint32_t* a,
                                        uint32_t b0, uint32_t b1) {
    asm volatile(
        "mma.sync.aligned.m16n8k16.row.col.f32.f16.f16.f32 "
        "{%0,%1,%2,%3}, {%4,%5,%6,%7}, {%8,%9}, {%0,%1,%2,%3};"
        : "+f"(c[0]), "+f"(c[1]), "+f"(c[2]), "+f"(c[3])
        : "r"(a[0]), "r"(a[1]), "r"(a[2]), "r"(a[3]), "r"(b0), "r"(b1));
}
__device__ __forceinline__ void cp_async16(uint32_t saddr, const void* gaddr) {
    asm volatile("cp.async.cg.shared.global [%0], [%1], 16;"
                 :: "r"(saddr), "l"(gaddr));
}

// ---------------- kernel A: convert (X -> fp16) + (W1 -> scaled/perm T) ----
// blocks [0,96): X split (4 float4/thread). blocks [96,608): W1 T+scale+perm.
__global__ void __launch_bounds__(512)
convert_kernel(const float* __restrict__ X, const float* __restrict__ W1,
               const float* __restrict__ W2, const float* __restrict__ b1) {
    const int tid = threadIdx.x;
    const int bx = blockIdx.x;
    if (bx < 96) {
#pragma unroll
        for (int q = 0; q < 4; q++) {
            int idx = bx * 2048 + q * 512 + tid;   // over 196608 float4
            float4 v = ((const float4*)X)[idx];
            ((__half2*)g_Xf)[idx * 2 + 0] = __floats2half2_rn(v.x, v.y);
            ((__half2*)g_Xf)[idx * 2 + 1] = __floats2half2_rn(v.z, v.w);
        }
    } else {
        __shared__ float t[32][33];
        __shared__ int   sperm[512];
        __shared__ float sw2a[512];
        __shared__ int   wcnt[16], wpre[17];

        // inlined deterministic sign-partition of h by sign(w2)
        const int lane = tid & 31, w = tid >> 5;
        float v2 = W2[tid];
        bool pos = (v2 >= 0.f);
        unsigned mset = __ballot_sync(0xffffffffu, pos);
        int lpre = __popc(mset & ((1u << lane) - 1u));
        if (lane == 0) wcnt[w] = __popc(mset);
        __syncthreads();
        if (tid == 0) {
            int s = 0;
#pragma unroll
            for (int k = 0; k < 16; k++) { wpre[k] = s; s += wcnt[k]; }
            wpre[16] = s;
        }
        __syncthreads();
        const int Hp = wpre[16];
        int posrank = wpre[w] + lpre;
        sperm[tid] = pos ? posrank : (Hp + tid - posrank);
        sw2a[tid] = fabsf(v2);
        __syncthreads();

        const int wb = bx - 96;                   // 0..511
        const int p  = wb >> 8;
        const int k0 = ((wb >> 4) & 15) * 32;
        const int n0 = (wb & 15) * 32;
        const int tx = tid & 31, ty = tid >> 5;   // (32,16)

        if (wb == 0 && tid == 0) g_Hpos = Hp;
        if (p == 0 && k0 == 0 && tid < 32) {
            int h = n0 + tid;
            g_b1s[sperm[h]] = b1[h] * sw2a[h];
        }
#pragma unroll
        for (int r = 0; r < 32; r += 16)
            t[ty + r][tx] = W1[(size_t)(p * 512 + k0 + ty + r) * 512 + n0 + tx];
        __syncthreads();
#pragma unroll
        for (int r = 0; r < 32; r += 16) {
            const int h = n0 + ty + r;
            float v = t[tx][ty + r] * sw2a[h];
            size_t o = (size_t)(p * 512 + sperm[h]) * 512 + k0 + tx;
            g_Wt[o] = __float2half_rn(v);
        }
    }
}

// ---------------- kernel B: fp16 GEMM, 192 blocks, tile 64m x 128n ---------
#define GASTRIDE 80
#define G_ATILE (64 * GASTRIDE)         // 5120
#define G_STAGE ((64 + 128) * GASTRIDE) // 15360
#define GEMM_SMEM (3 * G_STAGE)         // 46080

__global__ void __launch_bounds__(256)
gemm_mma_kernel() {
    extern __shared__ char smem[];
    const uint32_t smem_base = smem_u32(smem);
    const int tid = threadIdx.x, wid = tid >> 5, lane = tid & 31;
    const int n0 = blockIdx.x * 128;       // 0..896
    const int m0 = blockIdx.y * 64;        // 0..1472
    const int m_off  = (wid & 1) * 32;     // 2 m-warps
    const int n_woff = (wid >> 1) * 32;    // 4 n-warps

    const __half* srcA = g_Xf + (size_t)m0 * 512;
    const __half* srcB = g_Wt + (size_t)n0 * 512;

    // per-thread prefetch: 3 x 16B segments per stage (192 rows x 4 segs / 256)
    const __half* pr_[3];
    uint32_t      pd_[3];
#pragma unroll
    for (int it = 0; it < 3; it++) {
        const int t = it * 256 + tid;
        const int row = t >> 2, q = t & 3;
        pr_[it] = (row < 64) ? (srcA + (size_t)row * 512 + q * 8)
                             : (srcB + (size_t)(row - 64) * 512 + q * 8);
        pd_[it] = row * GASTRIDE + q * 16;  // row 64 lands exactly at G_ATILE
    }
    auto prefetch = [&](int c, int buf) {
        const uint32_t d = smem_base + buf * G_STAGE;
#pragma unroll
        for (int it = 0; it < 3; it++)
            cp_async16(d + pd_[it], pr_[it] + c * 32);
    };

    float acc[2][4][4];
#pragma unroll
    for (int i = 0; i < 2; i++)
#pragma unroll
        for (int j = 0; j < 4; j++)
#pragma unroll
            for (int k = 0; k < 4; k++) acc[i][j][k] = 0.f;

    const int grp = lane >> 3, ln8 = lane & 7;
    const int a_row = (grp & 1) * 8 + ln8;
    const int a_kB  = (grp >> 1) * 16;
    const int b_row = ((grp >> 1) & 1) * 8 + ln8;
    const int b_kB  = (grp & 1) * 16;

    prefetch(0, 0);
    asm volatile("cp.async.commit_group;" ::: "memory");
    prefetch(1, 1);
    asm volatile("cp.async.commit_group;" ::: "memory");

    for (int c = 0; c < 16; c++) {
        if (c + 2 < 16) {
            asm volatile("cp.async.wait_group 1;" ::: "memory");
        } else {
            asm volatile("cp.async.wait_group 0;" ::: "memory");
        }
        __syncthreads();
        if (c + 2 < 16) {
            prefetch(c + 2, (c + 2) % 3);
            asm volatile("cp.async.commit_group;" ::: "memory");
        }

        const uint32_t base = smem_base + (c % 3) * G_STAGE;
        const uint32_t Bb = base + G_ATILE;
#pragma unroll
        for (int ks = 0; ks < 2; ks++) {
            const int kB = ks * 32;
            uint32_t a[2][4], b[2][4];
#pragma unroll
            for (int fm = 0; fm < 2; fm++)
                ldsm_x4(a[fm], base + (m_off + fm * 16 + a_row) * GASTRIDE
                                    + kB + a_kB);
#pragma unroll
            for (int fp = 0; fp < 2; fp++)
                ldsm_x4(b[fp], Bb + (n_woff + fp * 16 + b_row) * GASTRIDE
                                  + kB + b_kB);
#pragma unroll
            for (int fm = 0; fm < 2; fm++)
#pragma unroll
                for (int fp = 0; fp < 2; fp++) {
                    mma_f16(acc[fm][2 * fp + 0], a[fm], b[fp][0], b[fp][1]);
                    mma_f16(acc[fm][2 * fp + 1], a[fm], b[fp][2], b[fp][3]);
                }
        }
        __syncthreads();
    }

    const bool isA = (n0 < 512);
    const int nbase = isA ? n0 : (n0 - 512);
    const int r0 = lane >> 2, cc = (lane & 3) * 2;

    // ---- C-half blocks: signed column sums -> g_v4 (deterministic) ----
    if (!isA) {
        const int Hpos = g_Hpos;
        float s[4] = {0.f, 0.f, 0.f, 0.f};
#pragma unroll
        for (int fm = 0; fm < 2; fm++)
#pragma unroll
            for (int fn = 0; fn < 4; fn++)
#pragma unroll
                for (int e = 0; e < 2; e++) {
                    const int l = n_woff + fn * 8 + cc + e;
                    const float sg = (nbase + l < Hpos) ? 1.f : -1.f;
                    s[fm * 2 + 0] += sg * acc[fm][fn][e];
                    s[fm * 2 + 1] += sg * acc[fm][fn][2 + e];
                }
#pragma unroll
        for (int q = 0; q < 4; q++) {
            s[q] += __shfl_xor_sync(0xffffffffu, s[q], 1);
            s[q] += __shfl_xor_sync(0xffffffffu, s[q], 2);
        }
        float* svv = (float*)smem;          // [4 n-warps][64 rows]
        if ((lane & 3) == 0) {
            const int nw = wid >> 1;
            svv[nw * 64 + m_off +  0 + r0] = s[0];
            svv[nw * 64 + m_off +  8 + r0] = s[1];
            svv[nw * 64 + m_off + 16 + r0] = s[2];
            svv[nw * 64 + m_off + 24 + r0] = s[3];
        }
        __syncthreads();
        if (tid < 64)
            g_v4[(blockIdx.x - 4) * M_ + m0 + tid] =
                svv[tid] + svv[64 + tid] + svv[128 + tid] + svv[192 + tid];
    }

    // b1s table for A-half blocks
    float* sb1 = (float*)smem;
    if (isA) {
        __syncthreads();
        if (tid < 128) sb1[tid] = g_b1s[n0 + tid];
        __syncthreads();
    }

    // epilogue: straight write, rows already permuted/scaled via Wt
    float* dstBase = isA ? g_AB2 : g_C2;
#pragma unroll
    for (int fm = 0; fm < 2; fm++) {
        const int mr0 = m0 + m_off + fm * 16 + r0;
        const int mr1 = mr0 + 8;
        const int b0r = mr0 / 96, i0r = mr0 - b0r * 96;
        const int b1r = mr1 / 96, i1r = mr1 - b1r * 96;
#pragma unroll
        for (int fn = 0; fn < 4; fn++) {
            const int lc = n_woff + fn * 8 + cc;
            const float* a4 = acc[fm][fn];
#pragma unroll
            for (int e = 0; e < 2; e++) {
                const int l = lc + e;
                const float add = isA ? sb1[l] : 0.f;
                dstBase[((size_t)(b0r * 512 + nbase + l)) * 96 + i0r] = a4[e] + add;
                dstBase[((size_t)(b1r * 512 + nbase + l)) * 96 + i1r] = a4[2 + e] + add;
            }
        }
    }
}

// ---------------- kernel D: pairwise abs-sum (64-h slices) -----------------
// grid (8 h-slices, 2 i-tiles, 16 b); 256 thr = 16(i) x 16(j); 3x6 per thread
__global__ void __launch_bounds__(256)
pairwise_kernel() {
    __shared__ __align__(16) float As[64 * 48];
    __shared__ __align__(16) float Cs[64 * 96];

    const int hs = blockIdx.x;
    const int it = blockIdx.y;
    const int b  = blockIdx.z;
    const int tid = threadIdx.x;
    const int ty = tid >> 4, tx = tid & 15;
    const int il = 3 * ty, jl = 6 * tx;

    const float4* srcA = (const float4*)(g_AB2 +
        ((size_t)(b * 512 + hs * 64)) * 96 + it * 48);
    const float4* srcC = (const float4*)(g_C2 +
        ((size_t)(b * 512 + hs * 64)) * 96);
    float4* dA = (float4*)As;
    float4* dC = (float4*)Cs;
#pragma unroll
    for (int t = tid; t < 768; t += 256) {
        int r = t / 12, q = t - r * 12;
        dA[t] = srcA[r * 24 + q];
    }
#pragma unroll
    for (int t = tid; t < 1536; t += 256)
        dC[t] = srcC[t];
    __syncthreads();

    const int bnd = min(max(g_Hpos - hs * 64, 0), 64);
    float acc[3][6] = {{0.f}};

    int h = 0;
#pragma unroll 4
    for (; h < bnd; h++) {
        const float* Ar = &As[h * 48 + il];
        const float* Cr = &Cs[h * 96 + jl];
        float a0 = Ar[0], a1 = Ar[1], a2 = Ar[2];
        float2 c01 = *(const float2*)&Cr[0];
        float2 c23 = *(const float2*)&Cr[2];
        float2 c45 = *(const float2*)&Cr[4];
        float cv[6] = {c01.x, c01.y, c23.x, c23.y, c45.x, c45.y};
#pragma unroll
        for (int c = 0; c < 6; c++) {
            acc[0][c] += fabsf(a0 + cv[c]);
            acc[1][c] += fabsf(a1 + cv[c]);
            acc[2][c] += fabsf(a2 + cv[c]);
        }
    }
#pragma unroll 4
    for (; h < 64; h++) {
        const float* Ar = &As[h * 48 + il];
        const float* Cr = &Cs[h * 96 + jl];
        float a0 = Ar[0], a1 = Ar[1], a2 = Ar[2];
        float2 c01 = *(const float2*)&Cr[0];
        float2 c23 = *(const float2*)&Cr[2];
        float2 c45 = *(const float2*)&Cr[4];
        float cv[6] = {c01.x, c01.y, c23.x, c23.y, c45.x, c45.y};
#pragma unroll
        for (int c = 0; c < 6; c++) {
            acc[0][c] -= fabsf(a0 + cv[c]);
            acc[1][c] -= fabsf(a1 + cv[c]);
            acc[2][c] -= fabsf(a2 + cv[c]);
        }
    }

    float* P = g_P + (size_t)hs * PSTRIDE +
               ((size_t)b * 96 + it * 48 + il) * 96 + jl;
#pragma unroll
    for (int r = 0; r < 3; r++) {
#pragma unroll
        for (int c = 0; c < 6; c += 2)
            *(float2*)&P[(size_t)r * 96 + c] = make_float2(acc[r][c], acc[r][c + 1]);
    }
}

// ---------------- kernel E: staged logits + softmax-CE (no atomics) --------
// grid (24, 16): block = 4 rows of batch b, 128 threads (4 warps).
__global__ void __launch_bounds__(128)
ce_kernel(const int* __restrict__ order) {
    __shared__ __align__(16) float lgs[4 * 96];
    __shared__ float vsh[96];
    __shared__ int   ord[96];
    __shared__ float wpart[4];

    const int b = blockIdx.y, tid = threadIdx.x;
    const int warp = tid >> 5, lane = tid & 31;
    const int i0 = blockIdx.x * 4;

    if (tid < 96) {
        vsh[tid] = g_v4[0 * M_ + b * 96 + tid] + g_v4[1 * M_ + b * 96 + tid]
                 + g_v4[2 * M_ + b * 96 + tid] + g_v4[3 * M_ + b * 96 + tid];
        ord[tid] = order[b * 96 + tid];
    }
    __syncthreads();

    // stage logits: 4 rows x 24 float4 = 96 threads, 8 slice-loads each
    if (tid < 96) {
        const int lr = tid / 24;          // local row 0..3
        const int j4 = tid % 24;          // float4 column
        const size_t base = (((size_t)b * 96 + i0 + lr) * 96) / 4 + j4;
        const float4* P4 = (const float4*)g_P;
        float4 s = make_float4(0.f, 0.f, 0.f, 0.f);
#pragma unroll
        for (int sl = 0; sl < NSLICE; sl++) {
            float4 p = P4[(size_t)sl * (PSTRIDE / 4) + base];
            s.x += p.x; s.y += p.y; s.z += p.z; s.w += p.w;
        }
        const int j = j4 * 4;
        float4 r;
        r.x = 0.45f * s.x + 0.55f * vsh[j + 0];
        r.y = 0.45f * s.y + 0.55f * vsh[j + 1];
        r.z = 0.45f * s.z + 0.55f * vsh[j + 2];
        r.w = 0.45f * s.w + 0.55f * vsh[j + 3];
        *(float4*)&lgs[lr * 96 + j] = r;
    }
    __syncthreads();

    // CE: warp handles row i0+warp
    const int i = i0 + warp;
    float l0 = lgs[warp * 96 + lane];
    float l1 = lgs[warp * 96 + lane + 32];
    float l2 = lgs[warp * 96 + lane + 64];

    float m = fmaxf(l0, fmaxf(l1, l2));
#pragma unroll
    for (int o = 16; o > 0; o >>= 1)
        m = fmaxf(m, __shfl_xor_sync(0xffffffffu, m, o));
    float s = expf(l0 - m) + expf(l1 - m) + expf(l2 - m);
#pragma unroll
    for (int o = 16; o > 0; o >>= 1)
        s += __shfl_xor_sync(0xffffffffu, s, o);
    float lse = m + logf(s);

    int oi = ord[i];
    int o0 = ord[lane], o1 = ord[lane + 32], o2 = ord[lane + 64];
    unsigned t0 = __ballot_sync(0xffffffffu, o0 == oi + 1);
    unsigned t1 = __ballot_sync(0xffffffffu, o1 == oi + 1);
    unsigned t2 = __ballot_sync(0xffffffffu, o2 == oi + 1);
    int tgt = t0 ? (__ffs(t0) - 1)
                 : (t1 ? (31 + __ffs(t1)) : (t2 ? (63 + __ffs(t2)) : 0));

    int mx = max(o0, max(o1, o2));
#pragma unroll
    for (int o = 16; o > 0; o >>= 1)
        mx = max(mx, __shfl_xor_sync(0xffffffffu, mx, o));
    unsigned M0 = __ballot_sync(0xffffffffu, o0 == mx);
    unsigned M1 = __ballot_sync(0xffffffffu, o1 == mx);
    unsigned M2 = __ballot_sync(0xffffffffu, o2 == mx);
    int last = M0 ? (__ffs(M0) - 1) : (M1 ? (31 + __ffs(M1)) : (63 + __ffs(M2)));

    float contrib = (i == last) ? 0.f : (lse - lgs[warp * 96 + tgt]);
    if (lane == 0) wpart[warp] = contrib;
    __syncthreads();
    if (tid == 0)
        g_partial[b * 24 + blockIdx.x] = wpart[0] + wpart[1] + wpart[2] + wpart[3];
}

// ---------------- kernel F: final reduce (1 block, same order as before) ---
__global__ void __launch_bounds__(128)
finalize_kernel(float* __restrict__ out) {
    __shared__ float wsum[4];
    const int tid = threadIdx.x, warp = tid >> 5, lane = tid & 31;
    float v = g_partial[tid] + g_partial[tid + 128] + g_partial[tid + 256];
#pragma unroll
    for (int o = 16; o > 0; o >>= 1)
        v += __shfl_xor_sync(0xffffffffu, v, o);
    if (lane == 0) wsum[warp] = v;
    __syncthreads();
    if (tid == 0)
        out[0] = (wsum[0] + wsum[1] + wsum[2] + wsum[3])
                 * (1.0f / (16.0f * 95.0f));
}

// ---------------- launcher --------------------------------------------------
extern "C" void kernel_launch(void* const* d_in, const int* in_sizes, int n_in,
                              void* d_out, int out_size) {
    const float* X    = (const float*)d_in[0];
    const float* W1   = (const float*)d_in[1];
    const float* b1   = (const float*)d_in[2];
    const float* W2   = (const float*)d_in[3];
    const int*   order = (const int*)d_in[6];

    static bool attr_set = false;
    if (!attr_set) {
        cudaFuncSetAttribute(gemm_mma_kernel,
                             cudaFuncAttributeMaxDynamicSharedMemorySize, GEMM_SMEM);
        attr_set = true;
    }

    convert_kernel<<<608, 512>>>(X, W1, W2, b1);
    gemm_mma_kernel<<<dim3(8, 24), 256, GEMM_SMEM>>>();
    pairwise_kernel<<<dim3(NSLICE, 2, 16), 256>>>();
    ce_kernel<<<dim3(24, 16), 128>>>(order);
    finalize_kernel<<<1, 128>>>((float*)d_out);
}